// round 1
// baseline (speedup 1.0000x reference)
#include <cuda_runtime.h>

// Problem constants
constexpr int Bb  = 2;
constexpr int Ll  = 2048;
constexpr int Hh  = 1024;
constexpr int NHh = 16;
constexpr int DHd = 64;

constexpr int GM = Bb * Ll;   // 4096 rows for all projections
constexpr int GN = Hh;        // 1024
constexpr int GK = Hh;        // 1024

// ---------------- device scratch (no allocations allowed) ----------------
__device__ float g_qp[Bb * Ll * Hh];
__device__ float g_kp[Bb * Ll * Hh];
__device__ float g_vp[Bb * Ll * Hh];
__device__ float g_atted[Bb * Ll * Hh];
__device__ float g_thr[Bb * Ll];
__device__ float g_colsum[Bb * Ll];

// ---------------- utility: zero a float buffer ----------------
__global__ void zero_kernel(float* __restrict__ p, int n) {
    int i = blockIdx.x * blockDim.x + threadIdx.x;
    if (i < n) p[i] = 0.f;
}

// ---------------- GEMM: C[M,N] = (gate.*A)[M,K] @ W[K,N] + bias ----------------
// BM=64, BN=64, BK=16, 256 threads, 4x4 microtile per thread.
template <bool GATED>
__global__ void __launch_bounds__(256) gemm_bias_kernel(
    const float* __restrict__ A, const float* __restrict__ W,
    const float* __restrict__ bias, float* __restrict__ C,
    const float* __restrict__ colsum, const float* __restrict__ thr)
{
    __shared__ __align__(16) float As[16][68];  // transposed [k][m], padded
    __shared__ __align__(16) float Bs[16][64];
    __shared__ float gate[64];

    const int t  = threadIdx.x;
    const int m0 = blockIdx.y * 64;
    const int n0 = blockIdx.x * 64;
    const int tx = t & 15;
    const int ty = t >> 4;

    const int am = t >> 2;          // 0..63 : A row within tile
    const int ak = (t & 3) * 4;     // 0,4,8,12 : A k-chunk
    const int bk = t >> 4;          // 0..15 : W row within tile
    const int bn = (t & 15) * 4;    // 0..60 : W col chunk

    if (GATED) {
        if (t < 64) gate[t] = ((colsum[m0 + t] - thr[m0 + t]) > 0.f) ? 1.f : 0.f;
        __syncthreads();
    }
    const float gv = GATED ? gate[am] : 1.f;

    float acc[4][4] = {};

    for (int k0 = 0; k0 < GK; k0 += 16) {
        float4 a = *(const float4*)&A[(size_t)(m0 + am) * GK + k0 + ak];
        a.x *= gv; a.y *= gv; a.z *= gv; a.w *= gv;
        As[ak + 0][am] = a.x;
        As[ak + 1][am] = a.y;
        As[ak + 2][am] = a.z;
        As[ak + 3][am] = a.w;
        *(float4*)&Bs[bk][bn] = *(const float4*)&W[(size_t)(k0 + bk) * GN + n0 + bn];
        __syncthreads();

        #pragma unroll
        for (int kk = 0; kk < 16; kk++) {
            float4 a4 = *(const float4*)&As[kk][ty * 4];
            float4 b4 = *(const float4*)&Bs[kk][tx * 4];
            acc[0][0] += a4.x * b4.x; acc[0][1] += a4.x * b4.y; acc[0][2] += a4.x * b4.z; acc[0][3] += a4.x * b4.w;
            acc[1][0] += a4.y * b4.x; acc[1][1] += a4.y * b4.y; acc[1][2] += a4.y * b4.z; acc[1][3] += a4.y * b4.w;
            acc[2][0] += a4.z * b4.x; acc[2][1] += a4.z * b4.y; acc[2][2] += a4.z * b4.z; acc[2][3] += a4.z * b4.w;
            acc[3][0] += a4.w * b4.x; acc[3][1] += a4.w * b4.y; acc[3][2] += a4.w * b4.z; acc[3][3] += a4.w * b4.w;
        }
        __syncthreads();
    }

    float4 bb = *(const float4*)&bias[n0 + tx * 4];
    #pragma unroll
    for (int i = 0; i < 4; i++) {
        int row = m0 + ty * 4 + i;
        float4 o;
        o.x = acc[i][0] + bb.x;
        o.y = acc[i][1] + bb.y;
        o.z = acc[i][2] + bb.z;
        o.w = acc[i][3] + bb.w;
        *(float4*)&C[(size_t)row * GN + n0 + tx * 4] = o;
    }
}

// ---------------- threshold: thr[row] = sum_i qp*kp*Wt + bt ----------------
__global__ void __launch_bounds__(128) threshold_kernel(
    const float* __restrict__ qp, const float* __restrict__ kp,
    const float* __restrict__ Wt, const float* __restrict__ bt,
    float* __restrict__ thr)
{
    __shared__ float red[4];
    const int row = blockIdx.x;
    const int t = threadIdx.x;
    const float* qr = qp + (size_t)row * Hh;
    const float* kr = kp + (size_t)row * Hh;
    float acc = 0.f;
    for (int i = t; i < Hh; i += 128) acc += qr[i] * kr[i] * Wt[i];
    #pragma unroll
    for (int o = 16; o; o >>= 1) acc += __shfl_xor_sync(0xffffffffu, acc, o);
    if ((t & 31) == 0) red[t >> 5] = acc;
    __syncthreads();
    if (t == 0) thr[row] = red[0] + red[1] + red[2] + red[3] + bt[0];
}

// ---------------- attention mega-kernel ----------------
// Block = (b, h, 16 query rows). Full score strip S[16][2048] kept in smem.
constexpr int QT = 16;
constexpr int KT = 128;
constexpr int NKT = Ll / KT;           // 16
constexpr int QT_STRIDE = 18;          // padded Q^T rows
constexpr int KT_STRIDE = 132;         // padded K^T rows (conflict-free scatter)
constexpr int V_STRIDE  = 68;          // padded V rows (16B-aligned float4)
constexpr int S_FLOATS  = QT * Ll;     // 32768
constexpr int KV_FLOATS = 8704;        // max(64*132, 128*68)
constexpr int ATTN_SMEM_FLOATS = S_FLOATS + 64 * QT_STRIDE + KV_FLOATS + 16;
constexpr int ATTN_SMEM = ATTN_SMEM_FLOATS * 4;  // 170560 bytes

__global__ void __launch_bounds__(256) attn_kernel(
    const float* __restrict__ qp, const float* __restrict__ kp,
    const float* __restrict__ vp, const unsigned char* __restrict__ mask,
    float* __restrict__ atted, float* __restrict__ colsum)
{
    extern __shared__ __align__(16) float sm[];
    float* S    = sm;                         // [16][2048]
    float* Qt   = sm + S_FLOATS;              // [64][18]  (Q transposed)
    float* KV   = Qt + 64 * QT_STRIDE;        // K^T [64][132]  /  V [128][68]
    float* invl = KV + KV_FLOATS;             // [16]

    const int t  = threadIdx.x;
    const int bx = blockIdx.x;
    const int qt = bx & 127;                  // L/QT = 128
    const int h  = (bx >> 7) & 15;
    const int b  = bx >> 11;
    const int q0 = qt * QT;
    const int hd = h * DHd;

    // ---- load Q tile transposed: Qt[d][r] ----
    for (int i = t; i < QT * DHd; i += 256) {
        int r = i >> 6, d = i & 63;
        Qt[d * QT_STRIDE + r] = qp[(size_t)(b * Ll + q0 + r) * Hh + hd + d];
    }

    const int ty = t >> 5;            // 0..7  -> rows {2ty, 2ty+1}
    const int tx = t & 31;            // 0..31 -> keys {4tx..4tx+3}
    const int kk = t & 127;           // key row this thread loads
    const int dh = (t >> 7) * 32;     // d-half this thread loads

    // ---- S = Q K^T / 8 over key tiles ----
    for (int kt = 0; kt < NKT; kt++) {
        const int k0 = kt * KT;
        const float* krow = kp + (size_t)(b * Ll + k0 + kk) * Hh + hd + dh;
        #pragma unroll
        for (int i = 0; i < 8; i++) {
            float4 v4 = *(const float4*)(krow + i * 4);
            KV[(dh + i * 4 + 0) * KT_STRIDE + kk] = v4.x;
            KV[(dh + i * 4 + 1) * KT_STRIDE + kk] = v4.y;
            KV[(dh + i * 4 + 2) * KT_STRIDE + kk] = v4.z;
            KV[(dh + i * 4 + 3) * KT_STRIDE + kk] = v4.w;
        }
        __syncthreads();

        float a00=0.f,a01=0.f,a02=0.f,a03=0.f,a10=0.f,a11=0.f,a12=0.f,a13=0.f;
        #pragma unroll 16
        for (int d = 0; d < 64; d++) {
            float2 q2 = *(const float2*)&Qt[d * QT_STRIDE + 2 * ty];
            float4 k4 = *(const float4*)&KV[d * KT_STRIDE + 4 * tx];
            a00 += q2.x * k4.x; a01 += q2.x * k4.y; a02 += q2.x * k4.z; a03 += q2.x * k4.w;
            a10 += q2.y * k4.x; a11 += q2.y * k4.y; a12 += q2.y * k4.z; a13 += q2.y * k4.w;
        }

        uchar4 mk = *(const uchar4*)(mask + b * Ll + k0 + 4 * tx);
        const float sc = 0.125f;
        float4 r0, r1;
        r0.x = mk.x ? -1e9f : a00 * sc;  r0.y = mk.y ? -1e9f : a01 * sc;
        r0.z = mk.z ? -1e9f : a02 * sc;  r0.w = mk.w ? -1e9f : a03 * sc;
        r1.x = mk.x ? -1e9f : a10 * sc;  r1.y = mk.y ? -1e9f : a11 * sc;
        r1.z = mk.z ? -1e9f : a12 * sc;  r1.w = mk.w ? -1e9f : a13 * sc;
        *(float4*)&S[(2 * ty)     * Ll + k0 + 4 * tx] = r0;
        *(float4*)&S[(2 * ty + 1) * Ll + k0 + 4 * tx] = r1;
        __syncthreads();
    }

    // ---- row stats: max, exp in place, 1/sum ----
    {
        const int w = t >> 5, lane = t & 31;
        #pragma unroll
        for (int rr = 0; rr < 2; rr++) {
            const int r = 2 * w + rr;
            float* Sr = S + r * Ll;
            float m = -1e30f;
            for (int j = lane; j < Ll; j += 32) m = fmaxf(m, Sr[j]);
            #pragma unroll
            for (int o = 16; o; o >>= 1) m = fmaxf(m, __shfl_xor_sync(0xffffffffu, m, o));
            float sum = 0.f;
            for (int j = lane; j < Ll; j += 32) {
                float e = __expf(Sr[j] - m);
                Sr[j] = e;
                sum += e;
            }
            #pragma unroll
            for (int o = 16; o; o >>= 1) sum += __shfl_xor_sync(0xffffffffu, sum, o);
            if (lane == 0) invl[r] = 1.f / sum;
        }
    }
    __syncthreads();

    // ---- colsum: per key, sum over this block's 16 normalized rows ----
    {
        float il[QT];
        #pragma unroll
        for (int r = 0; r < QT; r++) il[r] = invl[r];
        for (int k2 = t; k2 < Ll; k2 += 256) {
            float acc = 0.f;
            #pragma unroll
            for (int r = 0; r < QT; r++) acc += S[r * Ll + k2] * il[r];
            atomicAdd(&colsum[b * Ll + k2], acc);
        }
    }

    // ---- O = P V (unnormalized P in S, normalize at the end) ----
    const int row = t >> 4;          // 0..15
    const int dg  = (t & 15) * 4;    // 0..60
    float4 o = make_float4(0.f, 0.f, 0.f, 0.f);
    for (int vt = 0; vt < NKT; vt++) {
        const int v0 = vt * KT;
        __syncthreads();   // previous-tile KV reads done
        const float* vrow = vp + (size_t)(b * Ll + v0 + kk) * Hh + hd + dh;
        #pragma unroll
        for (int i = 0; i < 8; i++)
            *(float4*)&KV[kk * V_STRIDE + dh + i * 4] = *(const float4*)(vrow + i * 4);
        __syncthreads();

        const float* Sr = S + row * Ll + v0;
        #pragma unroll 16
        for (int k2 = 0; k2 < KT; k2++) {
            float p = Sr[k2];
            float4 v4 = *(const float4*)&KV[k2 * V_STRIDE + dg];
            o.x += p * v4.x; o.y += p * v4.y; o.z += p * v4.z; o.w += p * v4.w;
        }
    }
    const float il = invl[row];
    o.x *= il; o.y *= il; o.z *= il; o.w *= il;
    *(float4*)&atted[(size_t)(b * Ll + q0 + row) * Hh + hd + dg] = o;
}

// ---------------- launch ----------------
extern "C" void kernel_launch(void* const* d_in, const int* in_sizes, int n_in,
                              void* d_out, int out_size)
{
    const float* v  = (const float*)d_in[0];
    const float* k  = (const float*)d_in[1];
    const float* q  = (const float*)d_in[2];
    const unsigned char* mask = (const unsigned char*)d_in[3];
    const float* Wv = (const float*)d_in[4];
    const float* bv = (const float*)d_in[5];
    const float* Wk = (const float*)d_in[6];
    const float* bk = (const float*)d_in[7];
    const float* Wq = (const float*)d_in[8];
    const float* bq = (const float*)d_in[9];
    const float* Wt = (const float*)d_in[10];
    const float* bt = (const float*)d_in[11];
    const float* Wm = (const float*)d_in[12];
    const float* bm = (const float*)d_in[13];
    float* out = (float*)d_out;

    float *qp, *kp, *vp, *atted, *thr, *colsum;
    cudaGetSymbolAddress((void**)&qp,     g_qp);
    cudaGetSymbolAddress((void**)&kp,     g_kp);
    cudaGetSymbolAddress((void**)&vp,     g_vp);
    cudaGetSymbolAddress((void**)&atted,  g_atted);
    cudaGetSymbolAddress((void**)&thr,    g_thr);
    cudaGetSymbolAddress((void**)&colsum, g_colsum);

    cudaFuncSetAttribute(attn_kernel, cudaFuncAttributeMaxDynamicSharedMemorySize, ATTN_SMEM);

    zero_kernel<<<(Bb * Ll + 255) / 256, 256>>>(colsum, Bb * Ll);

    dim3 gg(GN / 64, GM / 64);
    gemm_bias_kernel<false><<<gg, 256>>>(q, Wq, bq, qp, nullptr, nullptr);
    gemm_bias_kernel<false><<<gg, 256>>>(k, Wk, bk, kp, nullptr, nullptr);
    gemm_bias_kernel<false><<<gg, 256>>>(v, Wv, bv, vp, nullptr, nullptr);

    threshold_kernel<<<Bb * Ll, 128>>>(qp, kp, Wt, bt, thr);

    attn_kernel<<<Bb * NHh * (Ll / QT), 256, ATTN_SMEM>>>(qp, kp, vp, mask, atted, colsum);

    gemm_bias_kernel<true><<<gg, 256>>>(atted, Wm, bm, out, colsum, thr);
}

// round 2
// speedup vs baseline: 1.8393x; 1.8393x over previous
#include <cuda_runtime.h>

// Problem constants
constexpr int Bb  = 2;
constexpr int Ll  = 2048;
constexpr int Hh  = 1024;
constexpr int NHh = 16;
constexpr int DHd = 64;

constexpr int GM = Bb * Ll;   // 4096
constexpr int GN = Hh;        // 1024
constexpr int GK = Hh;        // 1024

// ---------------- device scratch (no allocations allowed) ----------------
__device__ float g_qp[Bb * Ll * Hh];
__device__ float g_kp[Bb * Ll * Hh];
__device__ float g_vp[Bb * Ll * Hh];
__device__ float g_atted[Bb * Ll * Hh];
__device__ float g_thr[Bb * Ll];
__device__ float g_colsum[Bb * Ll];

// ---------------- utility: zero a float buffer ----------------
__global__ void zero_kernel(float* __restrict__ p, int n) {
    int i = blockIdx.x * blockDim.x + threadIdx.x;
    if (i < n) p[i] = 0.f;
}

// ---------------- tf32 mma helpers ----------------
__device__ __forceinline__ unsigned f2tf(float x) {
    unsigned u;
    asm("cvt.rna.tf32.f32 %0, %1;" : "=r"(u) : "f"(x));
    return u;
}

__device__ __forceinline__ void mma_tf32(
    float& c0, float& c1, float& c2, float& c3,
    unsigned a0, unsigned a1, unsigned a2, unsigned a3,
    unsigned b0, unsigned b1)
{
    asm volatile(
        "mma.sync.aligned.m16n8k8.row.col.f32.tf32.tf32.f32 "
        "{%0,%1,%2,%3},{%4,%5,%6,%7},{%8,%9},{%0,%1,%2,%3};"
        : "+f"(c0), "+f"(c1), "+f"(c2), "+f"(c3)
        : "r"(a0), "r"(a1), "r"(a2), "r"(a3), "r"(b0), "r"(b1));
}

// ---------------- GEMM: C[M,N] = (gate.*A)[M,K] @ W[K,N] + bias ----------------
template <bool GATED>
__global__ void __launch_bounds__(256) gemm_bias_kernel(
    const float* __restrict__ A, const float* __restrict__ W,
    const float* __restrict__ bias, float* __restrict__ C,
    const float* __restrict__ colsum, const float* __restrict__ thr)
{
    __shared__ __align__(16) float As[16][68];  // transposed [k][m], padded
    __shared__ __align__(16) float Bs[16][64];
    __shared__ float gate[64];

    const int t  = threadIdx.x;
    const int m0 = blockIdx.y * 64;
    const int n0 = blockIdx.x * 64;
    const int tx = t & 15;
    const int ty = t >> 4;

    const int am = t >> 2;
    const int ak = (t & 3) * 4;
    const int bk = t >> 4;
    const int bn = (t & 15) * 4;

    if (GATED) {
        if (t < 64) gate[t] = ((colsum[m0 + t] - thr[m0 + t]) > 0.f) ? 1.f : 0.f;
        __syncthreads();
    }
    const float gv = GATED ? gate[am] : 1.f;

    float acc[4][4] = {};

    for (int k0 = 0; k0 < GK; k0 += 16) {
        float4 a = *(const float4*)&A[(size_t)(m0 + am) * GK + k0 + ak];
        a.x *= gv; a.y *= gv; a.z *= gv; a.w *= gv;
        As[ak + 0][am] = a.x;
        As[ak + 1][am] = a.y;
        As[ak + 2][am] = a.z;
        As[ak + 3][am] = a.w;
        *(float4*)&Bs[bk][bn] = *(const float4*)&W[(size_t)(k0 + bk) * GN + n0 + bn];
        __syncthreads();

        #pragma unroll
        for (int kk = 0; kk < 16; kk++) {
            float4 a4 = *(const float4*)&As[kk][ty * 4];
            float4 b4 = *(const float4*)&Bs[kk][tx * 4];
            acc[0][0] += a4.x * b4.x; acc[0][1] += a4.x * b4.y; acc[0][2] += a4.x * b4.z; acc[0][3] += a4.x * b4.w;
            acc[1][0] += a4.y * b4.x; acc[1][1] += a4.y * b4.y; acc[1][2] += a4.y * b4.z; acc[1][3] += a4.y * b4.w;
            acc[2][0] += a4.z * b4.x; acc[2][1] += a4.z * b4.y; acc[2][2] += a4.z * b4.z; acc[2][3] += a4.z * b4.w;
            acc[3][0] += a4.w * b4.x; acc[3][1] += a4.w * b4.y; acc[3][2] += a4.w * b4.z; acc[3][3] += a4.w * b4.w;
        }
        __syncthreads();
    }

    float4 bb = *(const float4*)&bias[n0 + tx * 4];
    #pragma unroll
    for (int i = 0; i < 4; i++) {
        int row = m0 + ty * 4 + i;
        float4 o;
        o.x = acc[i][0] + bb.x;
        o.y = acc[i][1] + bb.y;
        o.z = acc[i][2] + bb.z;
        o.w = acc[i][3] + bb.w;
        *(float4*)&C[(size_t)row * GN + n0 + tx * 4] = o;
    }
}

// ---------------- threshold: thr[row] = sum_i qp*kp*Wt + bt ----------------
__global__ void __launch_bounds__(128) threshold_kernel(
    const float* __restrict__ qp, const float* __restrict__ kp,
    const float* __restrict__ Wt, const float* __restrict__ bt,
    float* __restrict__ thr)
{
    __shared__ float red[4];
    const int row = blockIdx.x;
    const int t = threadIdx.x;
    const float* qr = qp + (size_t)row * Hh;
    const float* kr = kp + (size_t)row * Hh;
    float acc = 0.f;
    for (int i = t; i < Hh; i += 128) acc += qr[i] * kr[i] * Wt[i];
    #pragma unroll
    for (int o = 16; o; o >>= 1) acc += __shfl_xor_sync(0xffffffffu, acc, o);
    if ((t & 31) == 0) red[t >> 5] = acc;
    __syncthreads();
    if (t == 0) thr[row] = red[0] + red[1] + red[2] + red[3] + bt[0];
}

// ---------------- attention mega-kernel (tf32 mma) ----------------
// Block = (b, h, 16 query rows). Full score strip S[16][2048] kept in smem.
constexpr int QT  = 16;
constexpr int KT  = 128;
constexpr int NKT = Ll / KT;     // 16

constexpr int SST = 2052;        // S stride (conflict-free frag loads: 2052%32==4)
constexpr int QST = 68;          // Q stride
constexpr int KST = 68;          // K tile stride (bank = 4g+t, distinct)
constexpr int VST = 72;          // V tile stride (bank = 8t+g, distinct)

constexpr int Q_OFF   = QT * SST;            // 32832
constexpr int KV_OFF  = Q_OFF + QT * QST;    // +1088
constexpr int INV_OFF = KV_OFF + KT * VST;   // +9216
constexpr int ATTN_FLOATS = INV_OFF + 16;
constexpr int ATTN_SMEM   = ATTN_FLOATS * 4; // 172,672 B

__global__ void __launch_bounds__(256) attn_kernel(
    const float* __restrict__ qp, const float* __restrict__ kp,
    const float* __restrict__ vp, const unsigned char* __restrict__ mask,
    float* __restrict__ atted, float* __restrict__ colsum)
{
    extern __shared__ __align__(16) float sm[];
    float* S    = sm;
    float* Qs   = sm + Q_OFF;
    float* KV   = sm + KV_OFF;
    float* invl = sm + INV_OFF;

    const int t    = threadIdx.x;
    const int w    = t >> 5;
    const int lane = t & 31;
    const int g    = lane >> 2;   // group id (rows / n-cols)
    const int tg   = lane & 3;    // thread in group

    const int bx = blockIdx.x;
    const int qt = bx & 127;
    const int h  = (bx >> 7) & 15;
    const int b  = bx >> 11;
    const int q0 = qt * QT;
    const int hd = h * DHd;

    // ---- load Q tile [16][64] ----
    for (int i = t; i < QT * DHd; i += 256) {
        int r = i >> 6, d = i & 63;
        Qs[r * QST + d] = qp[(size_t)(b * Ll + q0 + r) * Hh + hd + d];
    }
    __syncthreads();

    // ---- build A fragments for Q once (8 k-steps of 8) ----
    unsigned aq[8][4];
    #pragma unroll
    for (int ks = 0; ks < 8; ks++) {
        int c = ks * 8 + tg;
        aq[ks][0] = f2tf(Qs[g * QST + c]);
        aq[ks][1] = f2tf(Qs[(g + 8) * QST + c]);
        aq[ks][2] = f2tf(Qs[g * QST + c + 4]);
        aq[ks][3] = f2tf(Qs[(g + 8) * QST + c + 4]);
    }

    // ---- S = Q K^T / 8 (masked) ----
    for (int kt = 0; kt < NKT; kt++) {
        const int k0 = kt * KT;
        for (int j = t; j < KT * 16; j += 256) {        // 2048 float4s
            int row = j >> 4, c4 = (j & 15) * 4;
            *(float4*)&KV[row * KST + c4] =
                *(const float4*)&kp[(size_t)(b * Ll + k0 + row) * Hh + hd + c4];
        }
        __syncthreads();

        #pragma unroll
        for (int nt = 0; nt < 2; nt++) {
            const int n0 = w * 16 + nt * 8;             // keys within tile
            float c0 = 0.f, c1 = 0.f, c2 = 0.f, c3 = 0.f;
            #pragma unroll
            for (int ks = 0; ks < 8; ks++) {
                unsigned b0 = f2tf(KV[(n0 + g) * KST + ks * 8 + tg]);
                unsigned b1 = f2tf(KV[(n0 + g) * KST + ks * 8 + tg + 4]);
                mma_tf32(c0, c1, c2, c3,
                         aq[ks][0], aq[ks][1], aq[ks][2], aq[ks][3], b0, b1);
            }
            const int key = k0 + n0 + 2 * tg;
            unsigned char m0 = mask[b * Ll + key];
            unsigned char m1 = mask[b * Ll + key + 1];
            float2 r0, r1;
            r0.x = m0 ? -1e9f : c0 * 0.125f;  r0.y = m1 ? -1e9f : c1 * 0.125f;
            r1.x = m0 ? -1e9f : c2 * 0.125f;  r1.y = m1 ? -1e9f : c3 * 0.125f;
            *(float2*)&S[g * SST + key]       = r0;
            *(float2*)&S[(g + 8) * SST + key] = r1;
        }
        __syncthreads();
    }

    // ---- softmax rows: max, exp in place, 1/sum ----
    {
        #pragma unroll
        for (int rr = 0; rr < 2; rr++) {
            const int r = 2 * w + rr;
            float* Sr = S + r * SST;
            float m = -1e30f;
            for (int j = lane; j < Ll; j += 32) m = fmaxf(m, Sr[j]);
            #pragma unroll
            for (int o = 16; o; o >>= 1) m = fmaxf(m, __shfl_xor_sync(0xffffffffu, m, o));
            float sum = 0.f;
            for (int j = lane; j < Ll; j += 32) {
                float e = __expf(Sr[j] - m);
                Sr[j] = e;
                sum += e;
            }
            #pragma unroll
            for (int o = 16; o; o >>= 1) sum += __shfl_xor_sync(0xffffffffu, sum, o);
            if (lane == 0) invl[r] = 1.f / sum;
        }
    }
    __syncthreads();

    // ---- colsum: per key, sum over the 16 normalized rows ----
    {
        float il[QT];
        #pragma unroll
        for (int r = 0; r < QT; r++) il[r] = invl[r];
        for (int k2 = t; k2 < Ll; k2 += 256) {
            float acc = 0.f;
            #pragma unroll
            for (int r = 0; r < QT; r++) acc += S[r * SST + k2] * il[r];
            atomicAdd(&colsum[b * Ll + k2], acc);
        }
    }

    // ---- O = P V (unnormalized P in S), warp w owns d-cols [8w, 8w+8) ----
    const int n0 = w * 8;
    float o0 = 0.f, o1 = 0.f, o2 = 0.f, o3 = 0.f;
    for (int vt = 0; vt < NKT; vt++) {
        const int v0 = vt * KT;
        for (int j = t; j < KT * 16; j += 256) {
            int row = j >> 4, c4 = (j & 15) * 4;
            *(float4*)&KV[row * VST + c4] =
                *(const float4*)&vp[(size_t)(b * Ll + v0 + row) * Hh + hd + c4];
        }
        __syncthreads();

        #pragma unroll
        for (int ks = 0; ks < 16; ks++) {
            const int kk = ks * 8;
            unsigned a0 = f2tf(S[g * SST + v0 + kk + tg]);
            unsigned a1 = f2tf(S[(g + 8) * SST + v0 + kk + tg]);
            unsigned a2 = f2tf(S[g * SST + v0 + kk + tg + 4]);
            unsigned a3 = f2tf(S[(g + 8) * SST + v0 + kk + tg + 4]);
            unsigned b0 = f2tf(KV[(kk + tg) * VST + n0 + g]);
            unsigned b1 = f2tf(KV[(kk + tg + 4) * VST + n0 + g]);
            mma_tf32(o0, o1, o2, o3, a0, a1, a2, a3, b0, b1);
        }
        __syncthreads();
    }

    const float il0 = invl[g];
    const float il1 = invl[g + 8];
    const int dcol = hd + n0 + 2 * tg;
    float2 out0 = { o0 * il0, o1 * il0 };
    float2 out1 = { o2 * il1, o3 * il1 };
    *(float2*)&atted[(size_t)(b * Ll + q0 + g)     * Hh + dcol] = out0;
    *(float2*)&atted[(size_t)(b * Ll + q0 + g + 8) * Hh + dcol] = out1;
}

// ---------------- launch ----------------
extern "C" void kernel_launch(void* const* d_in, const int* in_sizes, int n_in,
                              void* d_out, int out_size)
{
    const float* v  = (const float*)d_in[0];
    const float* k  = (const float*)d_in[1];
    const float* q  = (const float*)d_in[2];
    const unsigned char* mask = (const unsigned char*)d_in[3];
    const float* Wv = (const float*)d_in[4];
    const float* bv = (const float*)d_in[5];
    const float* Wk = (const float*)d_in[6];
    const float* bk = (const float*)d_in[7];
    const float* Wq = (const float*)d_in[8];
    const float* bq = (const float*)d_in[9];
    const float* Wt = (const float*)d_in[10];
    const float* bt = (const float*)d_in[11];
    const float* Wm = (const float*)d_in[12];
    const float* bm = (const float*)d_in[13];
    float* out = (float*)d_out;

    float *qp, *kp, *vp, *atted, *thr, *colsum;
    cudaGetSymbolAddress((void**)&qp,     g_qp);
    cudaGetSymbolAddress((void**)&kp,     g_kp);
    cudaGetSymbolAddress((void**)&vp,     g_vp);
    cudaGetSymbolAddress((void**)&atted,  g_atted);
    cudaGetSymbolAddress((void**)&thr,    g_thr);
    cudaGetSymbolAddress((void**)&colsum, g_colsum);

    cudaFuncSetAttribute(attn_kernel, cudaFuncAttributeMaxDynamicSharedMemorySize, ATTN_SMEM);

    zero_kernel<<<(Bb * Ll + 255) / 256, 256>>>(colsum, Bb * Ll);

    dim3 gg(GN / 64, GM / 64);
    gemm_bias_kernel<false><<<gg, 256>>>(q, Wq, bq, qp, nullptr, nullptr);
    gemm_bias_kernel<false><<<gg, 256>>>(k, Wk, bk, kp, nullptr, nullptr);
    gemm_bias_kernel<false><<<gg, 256>>>(v, Wv, bv, vp, nullptr, nullptr);

    threshold_kernel<<<Bb * Ll, 128>>>(qp, kp, Wt, bt, thr);

    attn_kernel<<<Bb * NHh * (Ll / QT), 256, ATTN_SMEM>>>(qp, kp, vp, mask, atted, colsum);

    gemm_bias_kernel<true><<<gg, 256>>>(atted, Wm, bm, out, colsum, thr);
}

// round 3
// speedup vs baseline: 2.3185x; 1.2605x over previous
#include <cuda_runtime.h>

// Problem constants
constexpr int Bb  = 2;
constexpr int Ll  = 2048;
constexpr int Hh  = 1024;
constexpr int NHh = 16;
constexpr int DHd = 64;

constexpr int GM = Bb * Ll;   // 4096
constexpr int GN = Hh;        // 1024
constexpr int GK = Hh;        // 1024

// ---------------- device scratch ----------------
__device__ float g_qp[Bb * Ll * Hh];
__device__ float g_kp[Bb * Ll * Hh];
__device__ float g_vp[Bb * Ll * Hh];
__device__ float g_atted[Bb * Ll * Hh];
__device__ float g_thr[Bb * Ll];
__device__ float g_colsum[Bb * Ll];

__global__ void zero_kernel(float* __restrict__ p, int n) {
    int i = blockIdx.x * blockDim.x + threadIdx.x;
    if (i < n) p[i] = 0.f;
}

// ---------------- tf32 mma helpers ----------------
__device__ __forceinline__ unsigned f2tf(float x) {
    unsigned u;
    asm("cvt.rna.tf32.f32 %0, %1;" : "=r"(u) : "f"(x));
    return u;
}
__device__ __forceinline__ float f2tf_f(float x) {
    return __uint_as_float(f2tf(x));
}

__device__ __forceinline__ void mma_tf32(
    float& c0, float& c1, float& c2, float& c3,
    unsigned a0, unsigned a1, unsigned a2, unsigned a3,
    unsigned b0, unsigned b1)
{
    asm volatile(
        "mma.sync.aligned.m16n8k8.row.col.f32.tf32.tf32.f32 "
        "{%0,%1,%2,%3},{%4,%5,%6,%7},{%8,%9},{%0,%1,%2,%3};"
        : "+f"(c0), "+f"(c1), "+f"(c2), "+f"(c3)
        : "r"(a0), "r"(a1), "r"(a2), "r"(a3), "r"(b0), "r"(b1));
}

// ---------------- tf32 GEMM: C = gate.*(A @ W) + bias ----------------
// BM=64 BN=64 BK=16, 256 threads = 8 warps, each warp 16x32 via m16n8k8.
constexpr int AST = 20;   // As stride: bank (20g+tg)%32 distinct
constexpr int BST = 68;   // Bs stride: bank (4tg+g)%32 distinct

template <bool GATED>
__global__ void __launch_bounds__(256) gemm_tf32_kernel(
    const float* __restrict__ A, const float* __restrict__ W,
    const float* __restrict__ bias, float* __restrict__ C,
    const float* __restrict__ colsum, const float* __restrict__ thr)
{
    __shared__ __align__(16) float As[64 * AST];
    __shared__ __align__(16) float Bs[16 * BST];
    __shared__ float gate[64];

    const int t    = threadIdx.x;
    const int w    = t >> 5;
    const int lane = t & 31;
    const int g    = lane >> 2;
    const int tg   = lane & 3;
    const int wm   = (w & 3) * 16;   // m offset of warp tile
    const int wn   = (w >> 2) * 32;  // n offset of warp tile

    const int m0 = blockIdx.y * 64;
    const int n0 = blockIdx.x * 64;

    const int am = t >> 2;           // A row in tile
    const int ak = (t & 3) * 4;      // A k chunk
    const int bk = t >> 4;           // W row in tile
    const int bn = (t & 15) * 4;     // W col chunk

    if (GATED) {
        if (t < 64) gate[t] = ((colsum[m0 + t] - thr[m0 + t]) > 0.f) ? 1.f : 0.f;
    }

    float c[4][4] = {};

    for (int k0 = 0; k0 < GK; k0 += 16) {
        float4 a = *(const float4*)&A[(size_t)(m0 + am) * GK + k0 + ak];
        As[am * AST + ak + 0] = f2tf_f(a.x);
        As[am * AST + ak + 1] = f2tf_f(a.y);
        As[am * AST + ak + 2] = f2tf_f(a.z);
        As[am * AST + ak + 3] = f2tf_f(a.w);
        float4 bq = *(const float4*)&W[(size_t)(k0 + bk) * GN + n0 + bn];
        float4 bc = { f2tf_f(bq.x), f2tf_f(bq.y), f2tf_f(bq.z), f2tf_f(bq.w) };
        *(float4*)&Bs[bk * BST + bn] = bc;
        __syncthreads();

        #pragma unroll
        for (int ks = 0; ks < 2; ks++) {
            const int kb = ks * 8;
            unsigned a0 = __float_as_uint(As[(wm + g)     * AST + kb + tg]);
            unsigned a1 = __float_as_uint(As[(wm + g + 8) * AST + kb + tg]);
            unsigned a2 = __float_as_uint(As[(wm + g)     * AST + kb + tg + 4]);
            unsigned a3 = __float_as_uint(As[(wm + g + 8) * AST + kb + tg + 4]);
            #pragma unroll
            for (int nt = 0; nt < 4; nt++) {
                unsigned b0 = __float_as_uint(Bs[(kb + tg)     * BST + wn + nt * 8 + g]);
                unsigned b1 = __float_as_uint(Bs[(kb + tg + 4) * BST + wn + nt * 8 + g]);
                mma_tf32(c[nt][0], c[nt][1], c[nt][2], c[nt][3], a0, a1, a2, a3, b0, b1);
            }
        }
        __syncthreads();
    }

    const float gv0 = GATED ? gate[wm + g]     : 1.f;
    const float gv1 = GATED ? gate[wm + g + 8] : 1.f;
    #pragma unroll
    for (int nt = 0; nt < 4; nt++) {
        const int col = n0 + wn + nt * 8 + 2 * tg;
        float2 bb = *(const float2*)&bias[col];
        float2 o0 = { c[nt][0] * gv0 + bb.x, c[nt][1] * gv0 + bb.y };
        float2 o1 = { c[nt][2] * gv1 + bb.x, c[nt][3] * gv1 + bb.y };
        *(float2*)&C[(size_t)(m0 + wm + g)     * GN + col] = o0;
        *(float2*)&C[(size_t)(m0 + wm + g + 8) * GN + col] = o1;
    }
}

// ---------------- threshold ----------------
__global__ void __launch_bounds__(128) threshold_kernel(
    const float* __restrict__ qp, const float* __restrict__ kp,
    const float* __restrict__ Wt, const float* __restrict__ bt,
    float* __restrict__ thr)
{
    __shared__ float red[4];
    const int row = blockIdx.x;
    const int t = threadIdx.x;
    const float* qr = qp + (size_t)row * Hh;
    const float* kr = kp + (size_t)row * Hh;
    float acc = 0.f;
    for (int i = t; i < Hh; i += 128) acc += qr[i] * kr[i] * Wt[i];
    #pragma unroll
    for (int o = 16; o; o >>= 1) acc += __shfl_xor_sync(0xffffffffu, acc, o);
    if ((t & 31) == 0) red[t >> 5] = acc;
    __syncthreads();
    if (t == 0) thr[row] = red[0] + red[1] + red[2] + red[3] + bt[0];
}

// ---------------- attention mega-kernel (tf32 mma, 512 threads) ----------------
constexpr int QT  = 16;
constexpr int KT  = 128;
constexpr int NKT = Ll / KT;     // 16

constexpr int SST  = 2052;       // S stride: (4g+tg)%32 distinct
constexpr int KVST = 68;         // K/V tile stride: both frag patterns conflict-free

constexpr int Q_OFF   = QT * SST;                // Q stage / O reduction: 16*68
constexpr int KV_OFF  = Q_OFF + QT * KVST;       // two tiles of 128*68
constexpr int INV_OFF = KV_OFF + 2 * KT * KVST;
constexpr int ATTN_FLOATS = INV_OFF + 16;
constexpr int ATTN_SMEM   = ATTN_FLOATS * 4;     // ~205 KB

__global__ void __launch_bounds__(512) attn_kernel(
    const float* __restrict__ qp, const float* __restrict__ kp,
    const float* __restrict__ vp, const unsigned char* __restrict__ mask,
    float* __restrict__ atted, float* __restrict__ colsum)
{
    extern __shared__ __align__(16) float sm[];
    float* S    = sm;
    float* Qs   = sm + Q_OFF;     // also O-reduction buffer at the end
    float* KV0  = sm + KV_OFF;
    float* KV1  = KV0 + KT * KVST;
    float* invl = sm + INV_OFF;

    const int t    = threadIdx.x;
    const int w    = t >> 5;
    const int lane = t & 31;
    const int g    = lane >> 2;
    const int tg   = lane & 3;

    const int bx = blockIdx.x;
    const int qt = bx & 127;
    const int h  = (bx >> 7) & 15;
    const int b  = bx >> 11;
    const int q0 = qt * QT;
    const int hd = h * DHd;

    // ---- stage Q tile [16][64] ----
    for (int i = t; i < QT * DHd; i += 512) {
        int r = i >> 6, d = i & 63;
        Qs[r * KVST + d] = qp[(size_t)(b * Ll + q0 + r) * Hh + hd + d];
    }
    __syncthreads();

    // ---- Q fragments (tf32), reused over all key tiles ----
    unsigned aq[8][4];
    #pragma unroll
    for (int ks = 0; ks < 8; ks++) {
        int cc = ks * 8 + tg;
        aq[ks][0] = f2tf(Qs[g * KVST + cc]);
        aq[ks][1] = f2tf(Qs[(g + 8) * KVST + cc]);
        aq[ks][2] = f2tf(Qs[g * KVST + cc + 4]);
        aq[ks][3] = f2tf(Qs[(g + 8) * KVST + cc + 4]);
    }

    const int n0 = (w & 7) * 8 + (w >> 3) * 64;  // QK: warp key-group (0..15)*8
    // ---- S = Q K^T / 8 (masked) ----
    for (int kt = 0; kt < NKT; kt++) {
        const int k0 = kt * KT;
        __syncthreads();  // KV0 free
        #pragma unroll
        for (int i = 0; i < 4; i++) {
            int j = t + i * 512;
            int row = j >> 4, c4 = (j & 15) * 4;
            float4 v4 = *(const float4*)&kp[(size_t)(b * Ll + k0 + row) * Hh + hd + c4];
            float4 cv = { f2tf_f(v4.x), f2tf_f(v4.y), f2tf_f(v4.z), f2tf_f(v4.w) };
            *(float4*)&KV0[row * KVST + c4] = cv;
        }
        __syncthreads();

        float c0 = 0.f, c1 = 0.f, c2 = 0.f, c3 = 0.f;
        #pragma unroll
        for (int ks = 0; ks < 8; ks++) {
            unsigned b0 = __float_as_uint(KV0[(n0 + g) * KVST + ks * 8 + tg]);
            unsigned b1 = __float_as_uint(KV0[(n0 + g) * KVST + ks * 8 + tg + 4]);
            mma_tf32(c0, c1, c2, c3, aq[ks][0], aq[ks][1], aq[ks][2], aq[ks][3], b0, b1);
        }
        const int key = k0 + n0 + 2 * tg;
        unsigned char m0 = mask[b * Ll + key];
        unsigned char m1 = mask[b * Ll + key + 1];
        float2 r0, r1;
        r0.x = m0 ? -1e9f : c0 * 0.125f;  r0.y = m1 ? -1e9f : c1 * 0.125f;
        r1.x = m0 ? -1e9f : c2 * 0.125f;  r1.y = m1 ? -1e9f : c3 * 0.125f;
        *(float2*)&S[g * SST + key]       = r0;
        *(float2*)&S[(g + 8) * SST + key] = r1;
    }
    __syncthreads();

    // ---- softmax: warp w owns row w ----
    {
        float* Sr = S + w * SST;
        float m = -1e30f;
        for (int j = lane; j < Ll; j += 32) m = fmaxf(m, Sr[j]);
        #pragma unroll
        for (int o = 16; o; o >>= 1) m = fmaxf(m, __shfl_xor_sync(0xffffffffu, m, o));
        float sum = 0.f;
        for (int j = lane; j < Ll; j += 32) {
            float e = __expf(Sr[j] - m);
            Sr[j] = e;
            sum += e;
        }
        #pragma unroll
        for (int o = 16; o; o >>= 1) sum += __shfl_xor_sync(0xffffffffu, sum, o);
        if (lane == 0) invl[w] = 1.f / sum;
    }
    __syncthreads();

    // ---- colsum + in-place tf32 conversion of S ----
    {
        float il[QT];
        #pragma unroll
        for (int r = 0; r < QT; r++) il[r] = invl[r];
        for (int k2 = t; k2 < Ll; k2 += 512) {
            float acc = 0.f;
            #pragma unroll
            for (int r = 0; r < QT; r++) {
                float v = S[r * SST + k2];
                acc += v * il[r];
                S[r * SST + k2] = f2tf_f(v);
            }
            atomicAdd(&colsum[b * Ll + k2], acc);
        }
    }

    // ---- O = P V ; warps 0-7: even v-tiles, warps 8-15: odd v-tiles ----
    const int half = w >> 3;
    const int dn   = (w & 7) * 8;    // d-column group
    float o0 = 0.f, o1 = 0.f, o2 = 0.f, o3 = 0.f;

    for (int it = 0; it < NKT / 2; it++) {
        const int v0a = (2 * it) * KT;
        const int v0b = v0a + KT;
        __syncthreads();  // KV buffers free
        #pragma unroll
        for (int i = 0; i < 4; i++) {
            int j = t + i * 512;
            int row = j >> 4, c4 = (j & 15) * 4;
            float4 v4 = *(const float4*)&vp[(size_t)(b * Ll + v0a + row) * Hh + hd + c4];
            float4 cv = { f2tf_f(v4.x), f2tf_f(v4.y), f2tf_f(v4.z), f2tf_f(v4.w) };
            *(float4*)&KV0[row * KVST + c4] = cv;
            float4 u4 = *(const float4*)&vp[(size_t)(b * Ll + v0b + row) * Hh + hd + c4];
            float4 cu = { f2tf_f(u4.x), f2tf_f(u4.y), f2tf_f(u4.z), f2tf_f(u4.w) };
            *(float4*)&KV1[row * KVST + c4] = cu;
        }
        __syncthreads();

        const float* KVh = half ? KV1 : KV0;
        const int base = half ? v0b : v0a;
        #pragma unroll
        for (int ks = 0; ks < 16; ks++) {
            const int kk = ks * 8;
            unsigned a0 = __float_as_uint(S[g * SST + base + kk + tg]);
            unsigned a1 = __float_as_uint(S[(g + 8) * SST + base + kk + tg]);
            unsigned a2 = __float_as_uint(S[g * SST + base + kk + tg + 4]);
            unsigned a3 = __float_as_uint(S[(g + 8) * SST + base + kk + tg + 4]);
            unsigned b0 = __float_as_uint(KVh[(kk + tg) * KVST + dn + g]);
            unsigned b1 = __float_as_uint(KVh[(kk + tg + 4) * KVST + dn + g]);
            mma_tf32(o0, o1, o2, o3, a0, a1, a2, a3, b0, b1);
        }
    }
    __syncthreads();

    // ---- reduce the two halves through Qs, normalize, write out ----
    if (half) {
        *(float2*)&Qs[g * KVST + dn + 2 * tg]       = make_float2(o0, o1);
        *(float2*)&Qs[(g + 8) * KVST + dn + 2 * tg] = make_float2(o2, o3);
    }
    __syncthreads();
    if (!half) {
        float2 p0 = *(const float2*)&Qs[g * KVST + dn + 2 * tg];
        float2 p1 = *(const float2*)&Qs[(g + 8) * KVST + dn + 2 * tg];
        const float il0 = invl[g];
        const float il1 = invl[g + 8];
        float2 out0 = { (o0 + p0.x) * il0, (o1 + p0.y) * il0 };
        float2 out1 = { (o2 + p1.x) * il1, (o3 + p1.y) * il1 };
        const int dcol = hd + dn + 2 * tg;
        *(float2*)&atted[(size_t)(b * Ll + q0 + g)     * Hh + dcol] = out0;
        *(float2*)&atted[(size_t)(b * Ll + q0 + g + 8) * Hh + dcol] = out1;
    }
}

// ---------------- launch ----------------
extern "C" void kernel_launch(void* const* d_in, const int* in_sizes, int n_in,
                              void* d_out, int out_size)
{
    const float* v  = (const float*)d_in[0];
    const float* k  = (const float*)d_in[1];
    const float* q  = (const float*)d_in[2];
    const unsigned char* mask = (const unsigned char*)d_in[3];
    const float* Wv = (const float*)d_in[4];
    const float* bv = (const float*)d_in[5];
    const float* Wk = (const float*)d_in[6];
    const float* bk = (const float*)d_in[7];
    const float* Wq = (const float*)d_in[8];
    const float* bq = (const float*)d_in[9];
    const float* Wt = (const float*)d_in[10];
    const float* bt = (const float*)d_in[11];
    const float* Wm = (const float*)d_in[12];
    const float* bm = (const float*)d_in[13];
    float* out = (float*)d_out;

    float *qp, *kp, *vp, *atted, *thr, *colsum;
    cudaGetSymbolAddress((void**)&qp,     g_qp);
    cudaGetSymbolAddress((void**)&kp,     g_kp);
    cudaGetSymbolAddress((void**)&vp,     g_vp);
    cudaGetSymbolAddress((void**)&atted,  g_atted);
    cudaGetSymbolAddress((void**)&thr,    g_thr);
    cudaGetSymbolAddress((void**)&colsum, g_colsum);

    cudaFuncSetAttribute(attn_kernel, cudaFuncAttributeMaxDynamicSharedMemorySize, ATTN_SMEM);

    zero_kernel<<<(Bb * Ll + 255) / 256, 256>>>(colsum, Bb * Ll);

    dim3 gg(GN / 64, GM / 64);
    gemm_tf32_kernel<false><<<gg, 256>>>(q, Wq, bq, qp, nullptr, nullptr);
    gemm_tf32_kernel<false><<<gg, 256>>>(k, Wk, bk, kp, nullptr, nullptr);
    gemm_tf32_kernel<false><<<gg, 256>>>(v, Wv, bv, vp, nullptr, nullptr);

    threshold_kernel<<<Bb * Ll, 128>>>(qp, kp, Wt, bt, thr);

    attn_kernel<<<Bb * NHh * (Ll / QT), 512, ATTN_SMEM>>>(qp, kp, vp, mask, atted, colsum);

    gemm_tf32_kernel<true><<<gg, 256>>>(atted, Wm, bm, out, colsum, thr);
}

// round 4
// speedup vs baseline: 2.9901x; 1.2897x over previous
#include <cuda_runtime.h>

// Problem constants
constexpr int Bb  = 2;
constexpr int Ll  = 2048;
constexpr int Hh  = 1024;
constexpr int NHh = 16;
constexpr int DHd = 64;

constexpr int GM = Bb * Ll;   // 4096
constexpr int GN = Hh;        // 1024
constexpr int GK = Hh;        // 1024

// ---------------- device scratch ----------------
__device__ float g_qp[Bb * Ll * Hh];
__device__ float g_kp[Bb * Ll * Hh];
__device__ float g_vp[Bb * Ll * Hh];
__device__ float g_atted[Bb * Ll * Hh];
__device__ float g_thr[Bb * Ll];
__device__ float g_colsum[Bb * Ll];

__global__ void zero_kernel(float* __restrict__ p, int n) {
    int i = blockIdx.x * blockDim.x + threadIdx.x;
    if (i < n) p[i] = 0.f;
}

// ---------------- tf32 mma helpers ----------------
__device__ __forceinline__ unsigned f2tf(float x) {
    unsigned u;
    asm("cvt.rna.tf32.f32 %0, %1;" : "=r"(u) : "f"(x));
    return u;
}
__device__ __forceinline__ float f2tf_f(float x) {
    return __uint_as_float(f2tf(x));
}

__device__ __forceinline__ void mma_tf32(
    float& c0, float& c1, float& c2, float& c3,
    unsigned a0, unsigned a1, unsigned a2, unsigned a3,
    unsigned b0, unsigned b1)
{
    asm volatile(
        "mma.sync.aligned.m16n8k8.row.col.f32.tf32.tf32.f32 "
        "{%0,%1,%2,%3},{%4,%5,%6,%7},{%8,%9},{%0,%1,%2,%3};"
        : "+f"(c0), "+f"(c1), "+f"(c2), "+f"(c3)
        : "r"(a0), "r"(a1), "r"(a2), "r"(a3), "r"(b0), "r"(b1));
}

// monotone float<->uint key for atomicMax on floats of any sign
__device__ __forceinline__ unsigned f2key(float f) {
    unsigned b = __float_as_uint(f);
    return (b & 0x80000000u) ? ~b : (b | 0x80000000u);
}
__device__ __forceinline__ float key2f(unsigned u) {
    return __uint_as_float((u & 0x80000000u) ? (u & 0x7fffffffu) : ~u);
}

// ---------------- tf32 GEMM v2: C = gate.*(A @ W) + bias ----------------
// BM=64, BN=128, BK=16, 256 threads = 8 warps (2m x 4n), warp tile 32x32.
constexpr int AST = 20;    // As stride: banks (20g+tg)%32 distinct
constexpr int BST = 136;   // Bs stride: banks (8tg+g)%32 distinct

template <bool GATED>
__global__ void __launch_bounds__(256) gemm_tf32_kernel(
    const float* __restrict__ A, const float* __restrict__ W,
    const float* __restrict__ bias, float* __restrict__ C,
    const float* __restrict__ colsum, const float* __restrict__ thr)
{
    __shared__ __align__(16) float As[64 * AST];
    __shared__ __align__(16) float Bs[16 * BST];
    __shared__ float gate[64];

    const int t    = threadIdx.x;
    const int w    = t >> 5;
    const int lane = t & 31;
    const int g    = lane >> 2;
    const int tg   = lane & 3;
    const int wm   = (w & 1) * 32;
    const int wn   = (w >> 1) * 32;

    const int m0 = blockIdx.y * 64;
    const int n0 = blockIdx.x * 128;

    const int am = t >> 2;           // 0..63
    const int ak = (t & 3) * 4;      // 0,4,8,12
    const int brow = t >> 4;         // 0..15
    const int bcol = (t & 15) * 8;   // 0..120

    if (GATED && t < 64)
        gate[t] = ((colsum[m0 + t] - thr[m0 + t]) > 0.f) ? 1.f : 0.f;

    // prologue loads
    float4 ar  = *(const float4*)&A[(size_t)(m0 + am) * GK + ak];
    float4 br0 = *(const float4*)&W[(size_t)brow * GN + n0 + bcol];
    float4 br1 = *(const float4*)&W[(size_t)brow * GN + n0 + bcol + 4];

    float c[2][4][4] = {};

    for (int k0 = 0; k0 < GK; k0 += 16) {
        // stage current regs (tf32-rounded)
        float4 ac = { f2tf_f(ar.x), f2tf_f(ar.y), f2tf_f(ar.z), f2tf_f(ar.w) };
        *(float4*)&As[am * AST + ak] = ac;
        float4 bc0 = { f2tf_f(br0.x), f2tf_f(br0.y), f2tf_f(br0.z), f2tf_f(br0.w) };
        float4 bc1 = { f2tf_f(br1.x), f2tf_f(br1.y), f2tf_f(br1.z), f2tf_f(br1.w) };
        *(float4*)&Bs[brow * BST + bcol]     = bc0;
        *(float4*)&Bs[brow * BST + bcol + 4] = bc1;
        __syncthreads();

        if (k0 + 16 < GK) {
            ar  = *(const float4*)&A[(size_t)(m0 + am) * GK + k0 + 16 + ak];
            br0 = *(const float4*)&W[(size_t)(k0 + 16 + brow) * GN + n0 + bcol];
            br1 = *(const float4*)&W[(size_t)(k0 + 16 + brow) * GN + n0 + bcol + 4];
        }

        #pragma unroll
        for (int ks = 0; ks < 2; ks++) {
            const int kb = ks * 8;
            unsigned a[2][4];
            #pragma unroll
            for (int mt = 0; mt < 2; mt++) {
                const int r = wm + mt * 16 + g;
                a[mt][0] = __float_as_uint(As[r * AST + kb + tg]);
                a[mt][1] = __float_as_uint(As[(r + 8) * AST + kb + tg]);
                a[mt][2] = __float_as_uint(As[r * AST + kb + tg + 4]);
                a[mt][3] = __float_as_uint(As[(r + 8) * AST + kb + tg + 4]);
            }
            #pragma unroll
            for (int nt = 0; nt < 4; nt++) {
                unsigned b0 = __float_as_uint(Bs[(kb + tg)     * BST + wn + nt * 8 + g]);
                unsigned b1 = __float_as_uint(Bs[(kb + tg + 4) * BST + wn + nt * 8 + g]);
                #pragma unroll
                for (int mt = 0; mt < 2; mt++)
                    mma_tf32(c[mt][nt][0], c[mt][nt][1], c[mt][nt][2], c[mt][nt][3],
                             a[mt][0], a[mt][1], a[mt][2], a[mt][3], b0, b1);
            }
        }
        __syncthreads();
    }

    #pragma unroll
    for (int mt = 0; mt < 2; mt++) {
        const int r  = wm + mt * 16 + g;
        const float gv0 = GATED ? gate[r]     : 1.f;
        const float gv1 = GATED ? gate[r + 8] : 1.f;
        #pragma unroll
        for (int nt = 0; nt < 4; nt++) {
            const int col = n0 + wn + nt * 8 + 2 * tg;
            float2 bb = *(const float2*)&bias[col];
            float2 o0 = { c[mt][nt][0] * gv0 + bb.x, c[mt][nt][1] * gv0 + bb.y };
            float2 o1 = { c[mt][nt][2] * gv1 + bb.x, c[mt][nt][3] * gv1 + bb.y };
            *(float2*)&C[(size_t)(m0 + r)     * GN + col] = o0;
            *(float2*)&C[(size_t)(m0 + r + 8) * GN + col] = o1;
        }
    }
}

// ---------------- threshold ----------------
__global__ void __launch_bounds__(128) threshold_kernel(
    const float* __restrict__ qp, const float* __restrict__ kp,
    const float* __restrict__ Wt, const float* __restrict__ bt,
    float* __restrict__ thr)
{
    __shared__ float red[4];
    const int row = blockIdx.x;
    const int t = threadIdx.x;
    const float* qr = qp + (size_t)row * Hh;
    const float* kr = kp + (size_t)row * Hh;
    float acc = 0.f;
    for (int i = t; i < Hh; i += 128) acc += qr[i] * kr[i] * Wt[i];
    #pragma unroll
    for (int o = 16; o; o >>= 1) acc += __shfl_xor_sync(0xffffffffu, acc, o);
    if ((t & 31) == 0) red[t >> 5] = acc;
    __syncthreads();
    if (t == 0) thr[row] = red[0] + red[1] + red[2] + red[3] + bt[0];
}

// ---------------- attention mega-kernel v2 ----------------
constexpr int QT  = 16;
constexpr int KT  = 128;
constexpr int NKT = Ll / KT;     // 16

constexpr int SST = 2052;        // S stride
constexpr int QST = 68;          // Q stride (banks 4g+tg distinct)
constexpr int KST = 68;          // K tile stride (banks 4g+tg distinct)
constexpr int VST = 72;          // V tile stride (banks 8tg+g distinct)
constexpr int PST = 34;          // partial slab stride

constexpr int Q_OFF  = QT * SST;                 // 32832
constexpr int KB_OFF = Q_OFF + QT * QST;         // 33920
constexpr int KV_REGION = 2 * KT * VST;          // 18432 (covers 2*KT*KST too)
constexpr int RM_OFF  = KB_OFF + KV_REGION;      // 52352
constexpr int INV_OFF = RM_OFF + 16;             // 52368
constexpr int ATTN_FLOATS = INV_OFF + 16;        // 52384
constexpr int ATTN_SMEM   = ATTN_FLOATS * 4;     // 209536 B

__global__ void __launch_bounds__(512, 1) attn_kernel(
    const float* __restrict__ qp, const float* __restrict__ kp,
    const float* __restrict__ vp, const unsigned char* __restrict__ mask,
    float* __restrict__ atted, float* __restrict__ colsum)
{
    extern __shared__ __align__(16) float sm[];
    float* S  = sm;
    float* Qs = sm + Q_OFF;
    float* KB0 = sm + KB_OFF;
    float* KB1 = KB0 + KT * KST;
    float* VB0 = sm + KB_OFF;
    float* VB1 = VB0 + KT * VST;
    unsigned* rowmaxU = (unsigned*)(sm + RM_OFF);
    float* invl = sm + INV_OFF;

    const int t    = threadIdx.x;
    const int w    = t >> 5;
    const int lane = t & 31;
    const int g    = lane >> 2;
    const int tg   = lane & 3;

    const int bx = blockIdx.x;
    const int qt = bx & 127;
    const int h  = (bx >> 7) & 15;
    const int b  = bx >> 11;
    const int q0 = qt * QT;
    const int hd = h * DHd;

    // per-thread staging indices: 4 float4 per 128x64 tile
    const int srow0 = t >> 4;          // 0..31 (+32*i)
    const int sc4   = (t & 15) * 4;    // 0..60

    // ---- stage Q, init rowmax ----
    if (t < 16) rowmaxU[t] = 0u;
    for (int i = t; i < QT * DHd; i += 512) {
        int r = i >> 6, d = i & 63;
        Qs[r * QST + d] = qp[(size_t)(b * Ll + q0 + r) * Hh + hd + d];
    }
    __syncthreads();

    // ---- Q fragments (tf32) ----
    unsigned aq[8][4];
    #pragma unroll
    for (int ks = 0; ks < 8; ks++) {
        int cc = ks * 8 + tg;
        aq[ks][0] = f2tf(Qs[g * QST + cc]);
        aq[ks][1] = f2tf(Qs[(g + 8) * QST + cc]);
        aq[ks][2] = f2tf(Qs[g * QST + cc + 4]);
        aq[ks][3] = f2tf(Qs[(g + 8) * QST + cc + 4]);
    }

    const int n0 = (w & 7) * 8 + (w >> 3) * 64;   // warp key-slice (QK)

    // ---- QK: S = Q K^T / 8, double-buffered K tiles, running row max ----
    float lm0 = -1e30f, lm1 = -1e30f;
    float4 pre[4];

    #pragma unroll
    for (int i = 0; i < 4; i++)
        pre[i] = *(const float4*)&kp[(size_t)(b * Ll + 0 + srow0 + 32 * i) * Hh + hd + sc4];
    #pragma unroll
    for (int i = 0; i < 4; i++) {
        float4 cv = { f2tf_f(pre[i].x), f2tf_f(pre[i].y), f2tf_f(pre[i].z), f2tf_f(pre[i].w) };
        *(float4*)&KB0[(srow0 + 32 * i) * KST + sc4] = cv;
    }
    __syncthreads();

    for (int kt = 0; kt < NKT; kt++) {
        if (kt + 1 < NKT) {
            const int k1 = (kt + 1) * KT;
            #pragma unroll
            for (int i = 0; i < 4; i++)
                pre[i] = *(const float4*)&kp[(size_t)(b * Ll + k1 + srow0 + 32 * i) * Hh + hd + sc4];
        }
        const float* cur = (kt & 1) ? KB1 : KB0;

        float c0 = 0.f, c1 = 0.f, c2 = 0.f, c3 = 0.f;
        #pragma unroll
        for (int ks = 0; ks < 8; ks++) {
            unsigned b0 = __float_as_uint(cur[(n0 + g) * KST + ks * 8 + tg]);
            unsigned b1 = __float_as_uint(cur[(n0 + g) * KST + ks * 8 + tg + 4]);
            mma_tf32(c0, c1, c2, c3, aq[ks][0], aq[ks][1], aq[ks][2], aq[ks][3], b0, b1);
        }
        const int key = kt * KT + n0 + 2 * tg;
        unsigned char m0 = mask[b * Ll + key];
        unsigned char m1 = mask[b * Ll + key + 1];
        float2 r0, r1;
        r0.x = m0 ? -1e9f : c0 * 0.125f;  r0.y = m1 ? -1e9f : c1 * 0.125f;
        r1.x = m0 ? -1e9f : c2 * 0.125f;  r1.y = m1 ? -1e9f : c3 * 0.125f;
        lm0 = fmaxf(lm0, fmaxf(r0.x, r0.y));
        lm1 = fmaxf(lm1, fmaxf(r1.x, r1.y));
        *(float2*)&S[g * SST + key]       = r0;
        *(float2*)&S[(g + 8) * SST + key] = r1;

        if (kt + 1 < NKT) {
            float* nxt = (kt & 1) ? KB0 : KB1;
            #pragma unroll
            for (int i = 0; i < 4; i++) {
                float4 cv = { f2tf_f(pre[i].x), f2tf_f(pre[i].y), f2tf_f(pre[i].z), f2tf_f(pre[i].w) };
                *(float4*)&nxt[(srow0 + 32 * i) * KST + sc4] = cv;
            }
        }
        __syncthreads();
    }

    // ---- row max: shfl-reduce over tg then atomicMax ----
    lm0 = fmaxf(lm0, __shfl_xor_sync(0xffffffffu, lm0, 1));
    lm0 = fmaxf(lm0, __shfl_xor_sync(0xffffffffu, lm0, 2));
    lm1 = fmaxf(lm1, __shfl_xor_sync(0xffffffffu, lm1, 1));
    lm1 = fmaxf(lm1, __shfl_xor_sync(0xffffffffu, lm1, 2));
    if (tg == 0) {
        atomicMax(&rowmaxU[g],     f2key(lm0));
        atomicMax(&rowmaxU[g + 8], f2key(lm1));
    }
    __syncthreads();

    // ---- exp + row sum (tf32-rounded in place): warp w owns row w ----
    {
        const float m = key2f(rowmaxU[w]);
        float* Sr = S + w * SST;
        float sum = 0.f;
        for (int j = lane; j < Ll; j += 32) {
            float e = f2tf_f(__expf(Sr[j] - m));
            Sr[j] = e;
            sum += e;
        }
        #pragma unroll
        for (int o = 16; o; o >>= 1) sum += __shfl_xor_sync(0xffffffffu, sum, o);
        if (lane == 0) invl[w] = 1.f / sum;
    }
    __syncthreads();

    // ---- colsum (read-only S) + prologue V tile 0 staging ----
    #pragma unroll
    for (int i = 0; i < 4; i++)
        pre[i] = *(const float4*)&vp[(size_t)(b * Ll + 0 + srow0 + 32 * i) * Hh + hd + sc4];
    {
        float il[QT];
        #pragma unroll
        for (int r = 0; r < QT; r++) il[r] = invl[r];
        for (int k2 = t; k2 < Ll; k2 += 512) {
            float acc = 0.f;
            #pragma unroll
            for (int r = 0; r < QT; r++) acc += S[r * SST + k2] * il[r];
            atomicAdd(&colsum[b * Ll + k2], acc);
        }
    }
    #pragma unroll
    for (int i = 0; i < 4; i++) {
        float4 cv = { f2tf_f(pre[i].x), f2tf_f(pre[i].y), f2tf_f(pre[i].z), f2tf_f(pre[i].w) };
        *(float4*)&VB0[(srow0 + 32 * i) * VST + sc4] = cv;
    }
    __syncthreads();

    // ---- PV: warp = key-slice (w&7)*16 x d-half (w>>3)*32, persistent acc ----
    const int w8 = w & 7;
    const int dh = (w >> 3) * 32;
    float c[4][4] = {};

    for (int vt = 0; vt < NKT; vt++) {
        if (vt + 1 < NKT) {
            const int v1 = (vt + 1) * KT;
            #pragma unroll
            for (int i = 0; i < 4; i++)
                pre[i] = *(const float4*)&vp[(size_t)(b * Ll + v1 + srow0 + 32 * i) * Hh + hd + sc4];
        }
        const float* cur = (vt & 1) ? VB1 : VB0;
        const int sbase = vt * KT + w8 * 16;

        #pragma unroll
        for (int ks = 0; ks < 2; ks++) {
            const int kk = w8 * 16 + ks * 8;
            unsigned a0 = __float_as_uint(S[g * SST + sbase + ks * 8 + tg]);
            unsigned a1 = __float_as_uint(S[(g + 8) * SST + sbase + ks * 8 + tg]);
            unsigned a2 = __float_as_uint(S[g * SST + sbase + ks * 8 + tg + 4]);
            unsigned a3 = __float_as_uint(S[(g + 8) * SST + sbase + ks * 8 + tg + 4]);
            #pragma unroll
            for (int nt = 0; nt < 4; nt++) {
                unsigned b0 = __float_as_uint(cur[(kk + tg)     * VST + dh + nt * 8 + g]);
                unsigned b1 = __float_as_uint(cur[(kk + tg + 4) * VST + dh + nt * 8 + g]);
                mma_tf32(c[nt][0], c[nt][1], c[nt][2], c[nt][3], a0, a1, a2, a3, b0, b1);
            }
        }

        if (vt + 1 < NKT) {
            float* nxt = (vt & 1) ? VB0 : VB1;
            #pragma unroll
            for (int i = 0; i < 4; i++) {
                float4 cv = { f2tf_f(pre[i].x), f2tf_f(pre[i].y), f2tf_f(pre[i].z), f2tf_f(pre[i].w) };
                *(float4*)&nxt[(srow0 + 32 * i) * VST + sc4] = cv;
            }
        }
        __syncthreads();
    }

    // ---- 8-way reduction of key-slice partials through S region ----
    float* P = sm;   // 16 slabs of [16][PST]
    #pragma unroll
    for (int nt = 0; nt < 4; nt++) {
        *(float2*)&P[w * (16 * PST) + g * PST + nt * 8 + 2 * tg]       = make_float2(c[nt][0], c[nt][1]);
        *(float2*)&P[w * (16 * PST) + (g + 8) * PST + nt * 8 + 2 * tg] = make_float2(c[nt][2], c[nt][3]);
    }
    __syncthreads();

    for (int id = t; id < QT * DHd; id += 512) {
        const int r = id >> 6, d = id & 63;
        const int hf = d >> 5, dl = d & 31;
        float s = 0.f;
        #pragma unroll
        for (int sl = 0; sl < 8; sl++)
            s += P[(hf * 8 + sl) * (16 * PST) + r * PST + dl];
        atted[(size_t)(b * Ll + q0 + r) * Hh + hd + d] = s * invl[r];
    }
}

// ---------------- launch ----------------
extern "C" void kernel_launch(void* const* d_in, const int* in_sizes, int n_in,
                              void* d_out, int out_size)
{
    const float* v  = (const float*)d_in[0];
    const float* k  = (const float*)d_in[1];
    const float* q  = (const float*)d_in[2];
    const unsigned char* mask = (const unsigned char*)d_in[3];
    const float* Wv = (const float*)d_in[4];
    const float* bv = (const float*)d_in[5];
    const float* Wk = (const float*)d_in[6];
    const float* bk = (const float*)d_in[7];
    const float* Wq = (const float*)d_in[8];
    const float* bq = (const float*)d_in[9];
    const float* Wt = (const float*)d_in[10];
    const float* bt = (const float*)d_in[11];
    const float* Wm = (const float*)d_in[12];
    const float* bm = (const float*)d_in[13];
    float* out = (float*)d_out;

    float *qp, *kp, *vp, *atted, *thr, *colsum;
    cudaGetSymbolAddress((void**)&qp,     g_qp);
    cudaGetSymbolAddress((void**)&kp,     g_kp);
    cudaGetSymbolAddress((void**)&vp,     g_vp);
    cudaGetSymbolAddress((void**)&atted,  g_atted);
    cudaGetSymbolAddress((void**)&thr,    g_thr);
    cudaGetSymbolAddress((void**)&colsum, g_colsum);

    cudaFuncSetAttribute(attn_kernel, cudaFuncAttributeMaxDynamicSharedMemorySize, ATTN_SMEM);

    zero_kernel<<<(Bb * Ll + 255) / 256, 256>>>(colsum, Bb * Ll);

    dim3 gg(GN / 128, GM / 64);
    gemm_tf32_kernel<false><<<gg, 256>>>(q, Wq, bq, qp, nullptr, nullptr);
    gemm_tf32_kernel<false><<<gg, 256>>>(k, Wk, bk, kp, nullptr, nullptr);
    gemm_tf32_kernel<false><<<gg, 256>>>(v, Wv, bv, vp, nullptr, nullptr);

    threshold_kernel<<<Bb * Ll, 128>>>(qp, kp, Wt, bt, thr);

    attn_kernel<<<Bb * NHh * (Ll / QT), 512, ATTN_SMEM>>>(qp, kp, vp, mask, atted, colsum);

    gemm_tf32_kernel<true><<<gg, 256>>>(atted, Wm, bm, out, colsum, thr);
}

// round 5
// speedup vs baseline: 5.0589x; 1.6919x over previous
#include <cuda_runtime.h>
#include <cuda_fp16.h>

// Problem constants
constexpr int Bb  = 2;
constexpr int Ll  = 2048;
constexpr int Hh  = 1024;
constexpr int NHh = 16;
constexpr int DHd = 64;

constexpr int GM = Bb * Ll;   // 4096
constexpr int GN = Hh;        // 1024
constexpr int GK = Hh;        // 1024

// ---------------- device scratch ----------------
__device__ __half g_qp[Bb * Ll * Hh];
__device__ __half g_kp[Bb * Ll * Hh];
__device__ __half g_vp[Bb * Ll * Hh];
__device__ __half g_atted[Bb * Ll * Hh];
__device__ float  g_thr[Bb * Ll];
__device__ float  g_colsum[Bb * Ll];

__global__ void zero_kernel(float* __restrict__ p, int n) {
    int i = blockIdx.x * blockDim.x + threadIdx.x;
    if (i < n) p[i] = 0.f;
}

// ---------------- helpers ----------------
__device__ __forceinline__ unsigned f22h(float a, float b) {
    __half2 h = __floats2half2_rn(a, b);
    return *(unsigned*)&h;
}
__device__ __forceinline__ unsigned pack2(const __half* p0, const __half* p1) {
    unsigned lo = (unsigned)*(const unsigned short*)p0;
    unsigned hi = (unsigned)*(const unsigned short*)p1;
    return lo | (hi << 16);
}

__device__ __forceinline__ void mma_f16(
    float& c0, float& c1, float& c2, float& c3,
    unsigned a0, unsigned a1, unsigned a2, unsigned a3,
    unsigned b0, unsigned b1)
{
    asm volatile(
        "mma.sync.aligned.m16n8k16.row.col.f32.f16.f16.f32 "
        "{%0,%1,%2,%3},{%4,%5,%6,%7},{%8,%9},{%0,%1,%2,%3};"
        : "+f"(c0), "+f"(c1), "+f"(c2), "+f"(c3)
        : "r"(a0), "r"(a1), "r"(a2), "r"(a3), "r"(b0), "r"(b1));
}

// monotone float<->uint key for atomicMax on floats
__device__ __forceinline__ unsigned f2key(float f) {
    unsigned b = __float_as_uint(f);
    return (b & 0x80000000u) ? ~b : (b | 0x80000000u);
}
__device__ __forceinline__ float key2f(unsigned u) {
    return __uint_as_float((u & 0x80000000u) ? (u & 0x7fffffffu) : ~u);
}

// ---------------- fp16 GEMM: C = gate.*(A @ W) + bias ----------------
// BM=64, BN=128, BK=32, 256 threads = 8 warps (2m x 4n), warp tile 32x32.
constexpr int ASTH = 40;    // As stride (halves): banks 20g+tg distinct
constexpr int BSTH = 136;   // Bs stride (halves)

template <typename TA, typename TC, bool GATED>
__global__ void __launch_bounds__(256) gemm_f16_kernel(
    const TA* __restrict__ A, const float* __restrict__ W,
    const float* __restrict__ bias, TC* __restrict__ C,
    const float* __restrict__ colsum, const float* __restrict__ thr)
{
    __shared__ __align__(16) __half As[64 * ASTH];
    __shared__ __align__(16) __half Bs[32 * BSTH];
    __shared__ float gate[64];

    const int t    = threadIdx.x;
    const int w    = t >> 5;
    const int lane = t & 31;
    const int g    = lane >> 2;
    const int tg   = lane & 3;
    const int wm   = (w & 1) * 32;
    const int wn   = (w >> 1) * 32;

    const int m0 = blockIdx.y * 64;
    const int n0 = blockIdx.x * 128;

    const int am  = t >> 2;            // 0..63
    const int ak8 = (t & 3) * 8;       // 0,8,16,24
    const int br  = t >> 4;            // 0..15 (rows br, br+16)
    const int bc  = (t & 15) * 8;      // 0..120

    if (GATED && t < 64)
        gate[t] = ((colsum[m0 + t] - thr[m0 + t]) > 0.f) ? 1.f : 0.f;

    // prologue loads into regs
    uint4  arh;
    float4 ar0, ar1;
    if constexpr (sizeof(TA) == 2) {
        arh = *(const uint4*)&A[(size_t)(m0 + am) * GK + ak8];
    } else {
        ar0 = *(const float4*)&A[(size_t)(m0 + am) * GK + ak8];
        ar1 = *(const float4*)&A[(size_t)(m0 + am) * GK + ak8 + 4];
    }
    float4 wr[2][2];
    #pragma unroll
    for (int r = 0; r < 2; r++) {
        wr[r][0] = *(const float4*)&W[(size_t)(br + r * 16) * GN + n0 + bc];
        wr[r][1] = *(const float4*)&W[(size_t)(br + r * 16) * GN + n0 + bc + 4];
    }

    float c[2][4][4] = {};

    for (int k0 = 0; k0 < GK; k0 += 32) {
        // stage regs -> smem (fp16)
        if constexpr (sizeof(TA) == 2) {
            *(uint4*)&As[am * ASTH + ak8] = arh;
        } else {
            *(uint4*)&As[am * ASTH + ak8] = make_uint4(
                f22h(ar0.x, ar0.y), f22h(ar0.z, ar0.w),
                f22h(ar1.x, ar1.y), f22h(ar1.z, ar1.w));
        }
        #pragma unroll
        for (int r = 0; r < 2; r++)
            *(uint4*)&Bs[(br + r * 16) * BSTH + bc] = make_uint4(
                f22h(wr[r][0].x, wr[r][0].y), f22h(wr[r][0].z, wr[r][0].w),
                f22h(wr[r][1].x, wr[r][1].y), f22h(wr[r][1].z, wr[r][1].w));
        __syncthreads();

        if (k0 + 32 < GK) {
            if constexpr (sizeof(TA) == 2) {
                arh = *(const uint4*)&A[(size_t)(m0 + am) * GK + k0 + 32 + ak8];
            } else {
                ar0 = *(const float4*)&A[(size_t)(m0 + am) * GK + k0 + 32 + ak8];
                ar1 = *(const float4*)&A[(size_t)(m0 + am) * GK + k0 + 32 + ak8 + 4];
            }
            #pragma unroll
            for (int r = 0; r < 2; r++) {
                wr[r][0] = *(const float4*)&W[(size_t)(k0 + 32 + br + r * 16) * GN + n0 + bc];
                wr[r][1] = *(const float4*)&W[(size_t)(k0 + 32 + br + r * 16) * GN + n0 + bc + 4];
            }
        }

        #pragma unroll
        for (int kb = 0; kb < 32; kb += 16) {
            unsigned a[2][4];
            #pragma unroll
            for (int mt = 0; mt < 2; mt++) {
                const int r = wm + mt * 16 + g;
                a[mt][0] = *(const unsigned*)&As[r * ASTH + kb + 2 * tg];
                a[mt][1] = *(const unsigned*)&As[(r + 8) * ASTH + kb + 2 * tg];
                a[mt][2] = *(const unsigned*)&As[r * ASTH + kb + 2 * tg + 8];
                a[mt][3] = *(const unsigned*)&As[(r + 8) * ASTH + kb + 2 * tg + 8];
            }
            #pragma unroll
            for (int nt = 0; nt < 4; nt++) {
                const int col = wn + nt * 8 + g;
                unsigned b0 = pack2(&Bs[(kb + 2 * tg) * BSTH + col],
                                    &Bs[(kb + 2 * tg + 1) * BSTH + col]);
                unsigned b1 = pack2(&Bs[(kb + 2 * tg + 8) * BSTH + col],
                                    &Bs[(kb + 2 * tg + 9) * BSTH + col]);
                #pragma unroll
                for (int mt = 0; mt < 2; mt++)
                    mma_f16(c[mt][nt][0], c[mt][nt][1], c[mt][nt][2], c[mt][nt][3],
                            a[mt][0], a[mt][1], a[mt][2], a[mt][3], b0, b1);
            }
        }
        __syncthreads();
    }

    #pragma unroll
    for (int mt = 0; mt < 2; mt++) {
        const int r  = wm + mt * 16 + g;
        const float gv0 = GATED ? gate[r]     : 1.f;
        const float gv1 = GATED ? gate[r + 8] : 1.f;
        #pragma unroll
        for (int nt = 0; nt < 4; nt++) {
            const int col = n0 + wn + nt * 8 + 2 * tg;
            float2 bb = *(const float2*)&bias[col];
            float o00 = c[mt][nt][0] * gv0 + bb.x;
            float o01 = c[mt][nt][1] * gv0 + bb.y;
            float o10 = c[mt][nt][2] * gv1 + bb.x;
            float o11 = c[mt][nt][3] * gv1 + bb.y;
            if constexpr (sizeof(TC) == 2) {
                *(unsigned*)&C[(size_t)(m0 + r)     * GN + col] = f22h(o00, o01);
                *(unsigned*)&C[(size_t)(m0 + r + 8) * GN + col] = f22h(o10, o11);
            } else {
                *(float2*)&C[(size_t)(m0 + r)     * GN + col] = make_float2(o00, o01);
                *(float2*)&C[(size_t)(m0 + r + 8) * GN + col] = make_float2(o10, o11);
            }
        }
    }
}

// ---------------- threshold ----------------
__global__ void __launch_bounds__(128) threshold_kernel(
    const __half* __restrict__ qp, const __half* __restrict__ kp,
    const float* __restrict__ Wt, const float* __restrict__ bt,
    float* __restrict__ thr)
{
    __shared__ float red[4];
    const int row = blockIdx.x;
    const int t = threadIdx.x;
    const __half* qr = qp + (size_t)row * Hh;
    const __half* kr = kp + (size_t)row * Hh;
    float acc = 0.f;
    for (int i = t; i < Hh; i += 128)
        acc += __half2float(qr[i]) * __half2float(kr[i]) * Wt[i];
    #pragma unroll
    for (int o = 16; o; o >>= 1) acc += __shfl_xor_sync(0xffffffffu, acc, o);
    if ((t & 31) == 0) red[t >> 5] = acc;
    __syncthreads();
    if (t == 0) thr[row] = red[0] + red[1] + red[2] + red[3] + bt[0];
}

// ---------------- attention mega-kernel (fp16 mma) ----------------
constexpr int QT  = 16;
constexpr int KT  = 128;
constexpr int NKT = Ll / KT;     // 16

constexpr int SST   = 2052;      // S (fp32) stride
constexpr int PSTH  = SST * 2;   // P (half) stride, aliased onto S rows
constexpr int KVSTH = 72;        // K/V tile stride in halves (144B rows)
constexpr int QSTH  = 72;
constexpr int PST   = 34;        // fp32 reduction slab stride

constexpr int Q_OFF  = QT * SST;                   // 32832 floats
constexpr int KV_OFF = Q_OFF + (QT * QSTH) / 2;    // +576
constexpr int KVBUF  = (KT * KVSTH) / 2;           // 4608 floats per buffer
constexpr int RM_OFF  = KV_OFF + 2 * KVBUF;
constexpr int INV_OFF = RM_OFF + 16;
constexpr int ATTN_FLOATS = INV_OFF + 16;
constexpr int ATTN_SMEM   = ATTN_FLOATS * 4;       // 170,624 B

__global__ void __launch_bounds__(512, 1) attn_kernel(
    const __half* __restrict__ qp, const __half* __restrict__ kp,
    const __half* __restrict__ vp, const unsigned char* __restrict__ mask,
    __half* __restrict__ atted, float* __restrict__ colsum)
{
    extern __shared__ __align__(16) float sm[];
    float*  S   = sm;
    __half* P   = (__half*)sm;            // aliased onto S rows after exp
    __half* Qh  = (__half*)(sm + Q_OFF);
    __half* KB0 = (__half*)(sm + KV_OFF);
    __half* KB1 = KB0 + KT * KVSTH;
    unsigned* rowmaxU = (unsigned*)(sm + RM_OFF);
    float* invl = sm + INV_OFF;

    const int t    = threadIdx.x;
    const int w    = t >> 5;
    const int lane = t & 31;
    const int g    = lane >> 2;
    const int tg   = lane & 3;

    const int bx = blockIdx.x;
    const int qt = bx & 127;
    const int h  = (bx >> 7) & 15;
    const int b  = bx >> 11;
    const int q0 = qt * QT;
    const int hd = h * DHd;

    // staging indices: 2 uint4 (8 halves) per thread per 128x64 tile
    const int srow = t >> 3;           // 0..63 (and +64)
    const int sc8  = (t & 7) * 8;

    const __half* kbase = kp + ((size_t)b * Ll) * Hh + hd;
    const __half* vbase = vp + ((size_t)b * Ll) * Hh + hd;

    // ---- stage Q, init rowmax ----
    if (t < 16) rowmaxU[t] = 0u;
    if (t < 128) {
        int r = t >> 3, c8 = (t & 7) * 8;
        *(uint4*)&Qh[r * QSTH + c8] =
            *(const uint4*)&qp[(size_t)(b * Ll + q0 + r) * Hh + hd + c8];
    }
    __syncthreads();

    // ---- Q fragments (4 k-steps of 16) ----
    unsigned aq[4][4];
    #pragma unroll
    for (int ks = 0; ks < 4; ks++) {
        const int cc = ks * 16 + 2 * tg;
        aq[ks][0] = *(const unsigned*)&Qh[g * QSTH + cc];
        aq[ks][1] = *(const unsigned*)&Qh[(g + 8) * QSTH + cc];
        aq[ks][2] = *(const unsigned*)&Qh[g * QSTH + cc + 8];
        aq[ks][3] = *(const unsigned*)&Qh[(g + 8) * QSTH + cc + 8];
    }

    const int n0 = (w & 7) * 8 + (w >> 3) * 64;   // warp key-slice (QK)

    // ---- QK: S = Q K^T / 8, double-buffered K tiles, running row max ----
    float lm0 = -1e30f, lm1 = -1e30f;
    uint4 pre0, pre1;

    pre0 = *(const uint4*)&kbase[(size_t)srow * Hh + sc8];
    pre1 = *(const uint4*)&kbase[(size_t)(srow + 64) * Hh + sc8];
    *(uint4*)&KB0[srow * KVSTH + sc8]        = pre0;
    *(uint4*)&KB0[(srow + 64) * KVSTH + sc8] = pre1;
    __syncthreads();

    for (int kt = 0; kt < NKT; kt++) {
        if (kt + 1 < NKT) {
            const size_t rb = (size_t)((kt + 1) * KT) * Hh;
            pre0 = *(const uint4*)&kbase[rb + (size_t)srow * Hh + sc8];
            pre1 = *(const uint4*)&kbase[rb + (size_t)(srow + 64) * Hh + sc8];
        }
        const __half* cur = (kt & 1) ? KB1 : KB0;

        float c0 = 0.f, c1 = 0.f, c2 = 0.f, c3 = 0.f;
        #pragma unroll
        for (int ks = 0; ks < 4; ks++) {
            const int cc = ks * 16 + 2 * tg;
            unsigned b0 = *(const unsigned*)&cur[(n0 + g) * KVSTH + cc];
            unsigned b1 = *(const unsigned*)&cur[(n0 + g) * KVSTH + cc + 8];
            mma_f16(c0, c1, c2, c3, aq[ks][0], aq[ks][1], aq[ks][2], aq[ks][3], b0, b1);
        }
        const int key = kt * KT + n0 + 2 * tg;
        unsigned char m0 = mask[b * Ll + key];
        unsigned char m1 = mask[b * Ll + key + 1];
        float2 r0, r1;
        r0.x = m0 ? -1e9f : c0 * 0.125f;  r0.y = m1 ? -1e9f : c1 * 0.125f;
        r1.x = m0 ? -1e9f : c2 * 0.125f;  r1.y = m1 ? -1e9f : c3 * 0.125f;
        lm0 = fmaxf(lm0, fmaxf(r0.x, r0.y));
        lm1 = fmaxf(lm1, fmaxf(r1.x, r1.y));
        *(float2*)&S[g * SST + key]       = r0;
        *(float2*)&S[(g + 8) * SST + key] = r1;

        if (kt + 1 < NKT) {
            __half* nxt = (kt & 1) ? KB0 : KB1;
            *(uint4*)&nxt[srow * KVSTH + sc8]        = pre0;
            *(uint4*)&nxt[(srow + 64) * KVSTH + sc8] = pre1;
        }
        __syncthreads();
    }

    // ---- row max ----
    lm0 = fmaxf(lm0, __shfl_xor_sync(0xffffffffu, lm0, 1));
    lm0 = fmaxf(lm0, __shfl_xor_sync(0xffffffffu, lm0, 2));
    lm1 = fmaxf(lm1, __shfl_xor_sync(0xffffffffu, lm1, 1));
    lm1 = fmaxf(lm1, __shfl_xor_sync(0xffffffffu, lm1, 2));
    if (tg == 0) {
        atomicMax(&rowmaxU[g],     f2key(lm0));
        atomicMax(&rowmaxU[g + 8], f2key(lm1));
    }
    __syncthreads();

    // ---- exp: read fp32 S row, write half P into row prefix; row sum ----
    {
        const float m = key2f(rowmaxU[w]);
        const float* Sr = S + w * SST;
        __half* Pr = P + w * PSTH;
        float sum = 0.f;
        #pragma unroll 4
        for (int i = 0; i < 32; i++) {
            const int cc = i * 64 + 2 * lane;
            float2 v = *(const float2*)&Sr[cc];
            float e0 = __expf(v.x - m);
            float e1 = __expf(v.y - m);
            sum += e0 + e1;
            if (i == 0) __syncwarp();
            *(unsigned*)&Pr[cc] = f22h(e0, e1);
        }
        #pragma unroll
        for (int o = 16; o; o >>= 1) sum += __shfl_xor_sync(0xffffffffu, sum, o);
        if (lane == 0) invl[w] = 1.f / sum;
    }
    __syncthreads();

    // ---- colsum (reads P half) + V tile-0 prologue ----
    pre0 = *(const uint4*)&vbase[(size_t)srow * Hh + sc8];
    pre1 = *(const uint4*)&vbase[(size_t)(srow + 64) * Hh + sc8];
    {
        float il[QT];
        #pragma unroll
        for (int r = 0; r < QT; r++) il[r] = invl[r];
        for (int k2 = t; k2 < Ll; k2 += 512) {
            float acc = 0.f;
            #pragma unroll
            for (int r = 0; r < QT; r++)
                acc += __half2float(P[r * PSTH + k2]) * il[r];
            atomicAdd(&colsum[b * Ll + k2], acc);
        }
    }
    *(uint4*)&KB0[srow * KVSTH + sc8]        = pre0;
    *(uint4*)&KB0[(srow + 64) * KVSTH + sc8] = pre1;
    __syncthreads();

    // ---- PV: warp = key-slice (w&7)*16 x d-half (w>>3)*32 ----
    const int sk = (w & 7) * 16;     // within-tile key offset
    const int dh = (w >> 3) * 32;
    float c[4][4] = {};

    for (int vt = 0; vt < NKT; vt++) {
        if (vt + 1 < NKT) {
            const size_t rb = (size_t)((vt + 1) * KT) * Hh;
            pre0 = *(const uint4*)&vbase[rb + (size_t)srow * Hh + sc8];
            pre1 = *(const uint4*)&vbase[rb + (size_t)(srow + 64) * Hh + sc8];
        }
        const __half* cur = (vt & 1) ? KB1 : KB0;
        const int key0 = vt * KT + sk;

        unsigned a0 = *(const unsigned*)&P[g * PSTH + key0 + 2 * tg];
        unsigned a1 = *(const unsigned*)&P[(g + 8) * PSTH + key0 + 2 * tg];
        unsigned a2 = *(const unsigned*)&P[g * PSTH + key0 + 2 * tg + 8];
        unsigned a3 = *(const unsigned*)&P[(g + 8) * PSTH + key0 + 2 * tg + 8];

        #pragma unroll
        for (int nt = 0; nt < 4; nt++) {
            const int dcol = dh + nt * 8 + g;
            unsigned b0 = pack2(&cur[(sk + 2 * tg) * KVSTH + dcol],
                                &cur[(sk + 2 * tg + 1) * KVSTH + dcol]);
            unsigned b1 = pack2(&cur[(sk + 2 * tg + 8) * KVSTH + dcol],
                                &cur[(sk + 2 * tg + 9) * KVSTH + dcol]);
            mma_f16(c[nt][0], c[nt][1], c[nt][2], c[nt][3], a0, a1, a2, a3, b0, b1);
        }

        if (vt + 1 < NKT) {
            __half* nxt = (vt & 1) ? KB0 : KB1;
            *(uint4*)&nxt[srow * KVSTH + sc8]        = pre0;
            *(uint4*)&nxt[(srow + 64) * KVSTH + sc8] = pre1;
        }
        __syncthreads();
    }

    // ---- 8-way reduction of key-slice partials through sm base region ----
    float* R = sm;   // 16 slabs of [16][PST]  (P/S dead now)
    #pragma unroll
    for (int nt = 0; nt < 4; nt++) {
        *(float2*)&R[w * (16 * PST) + g * PST + (w >> 3) * 0 + nt * 8 + 2 * tg]
            = make_float2(c[nt][0], c[nt][1]);
        *(float2*)&R[w * (16 * PST) + (g + 8) * PST + nt * 8 + 2 * tg]
            = make_float2(c[nt][2], c[nt][3]);
    }
    __syncthreads();

    for (int id = t; id < QT * DHd; id += 512) {
        const int r = id >> 6, d = id & 63;
        const int hf = d >> 5, dl = d & 31;
        float s = 0.f;
        #pragma unroll
        for (int sl = 0; sl < 8; sl++)
            s += R[(hf * 8 + sl) * (16 * PST) + r * PST + dl];
        atted[(size_t)(b * Ll + q0 + r) * Hh + hd + d] = __float2half_rn(s * invl[r]);
    }
}

// ---------------- launch ----------------
extern "C" void kernel_launch(void* const* d_in, const int* in_sizes, int n_in,
                              void* d_out, int out_size)
{
    const float* v  = (const float*)d_in[0];
    const float* k  = (const float*)d_in[1];
    const float* q  = (const float*)d_in[2];
    const unsigned char* mask = (const unsigned char*)d_in[3];
    const float* Wv = (const float*)d_in[4];
    const float* bv = (const float*)d_in[5];
    const float* Wk = (const float*)d_in[6];
    const float* bk = (const float*)d_in[7];
    const float* Wq = (const float*)d_in[8];
    const float* bq = (const float*)d_in[9];
    const float* Wt = (const float*)d_in[10];
    const float* bt = (const float*)d_in[11];
    const float* Wm = (const float*)d_in[12];
    const float* bm = (const float*)d_in[13];
    float* out = (float*)d_out;

    __half *qp, *kp, *vp, *atted;
    float *thr, *colsum;
    cudaGetSymbolAddress((void**)&qp,     g_qp);
    cudaGetSymbolAddress((void**)&kp,     g_kp);
    cudaGetSymbolAddress((void**)&vp,     g_vp);
    cudaGetSymbolAddress((void**)&atted,  g_atted);
    cudaGetSymbolAddress((void**)&thr,    g_thr);
    cudaGetSymbolAddress((void**)&colsum, g_colsum);

    cudaFuncSetAttribute(attn_kernel, cudaFuncAttributeMaxDynamicSharedMemorySize, ATTN_SMEM);

    zero_kernel<<<(Bb * Ll + 255) / 256, 256>>>(colsum, Bb * Ll);

    dim3 gg(GN / 128, GM / 64);
    gemm_f16_kernel<float, __half, false><<<gg, 256>>>(q, Wq, bq, qp, nullptr, nullptr);
    gemm_f16_kernel<float, __half, false><<<gg, 256>>>(k, Wk, bk, kp, nullptr, nullptr);
    gemm_f16_kernel<float, __half, false><<<gg, 256>>>(v, Wv, bv, vp, nullptr, nullptr);

    threshold_kernel<<<Bb * Ll, 128>>>(qp, kp, Wt, bt, thr);

    attn_kernel<<<Bb * NHh * (Ll / QT), 512, ATTN_SMEM>>>(qp, kp, vp, mask, atted, colsum);

    gemm_f16_kernel<__half, float, true><<<gg, 256>>>(atted, Wm, bm, out, colsum, thr);
}

// round 6
// speedup vs baseline: 9.4934x; 1.8766x over previous
#include <cuda_runtime.h>
#include <cuda_fp16.h>

// Problem constants
constexpr int Bb  = 2;
constexpr int Ll  = 2048;
constexpr int Hh  = 1024;
constexpr int NHh = 16;
constexpr int DHd = 64;

constexpr int GM = Bb * Ll;   // 4096
constexpr int GN = Hh;        // 1024
constexpr int GK = Hh;        // 1024

// ---------------- device scratch ----------------
__device__ __half g_qh[GM * Hh];
__device__ __half g_kh[GM * Hh];
__device__ __half g_vh[GM * Hh];
__device__ __half g_Wqh[Hh * Hh];
__device__ __half g_Wkh[Hh * Hh];
__device__ __half g_Wvh[Hh * Hh];
__device__ __half g_Wmh[Hh * Hh];
__device__ __half g_qp[GM * Hh];
__device__ __half g_kp[GM * Hh];
__device__ __half g_vp[GM * Hh];
__device__ __half g_atted[GM * Hh];
__device__ float  g_thr[GM];
__device__ float  g_colsum[GM];

// ---------------- helpers ----------------
__device__ __forceinline__ unsigned f22h(float a, float b) {
    __half2 h = __floats2half2_rn(a, b);
    return *(unsigned*)&h;
}

__device__ __forceinline__ unsigned smem_u32(const void* p) {
    unsigned a;
    asm("{ .reg .u64 t; cvta.to.shared.u64 t, %1; cvt.u32.u64 %0, t; }" : "=r"(a) : "l"(p));
    return a;
}

__device__ __forceinline__ void cp16(unsigned dst, const void* src) {
    asm volatile("cp.async.cg.shared.global [%0], [%1], 16;" :: "r"(dst), "l"(src));
}
#define CP_COMMIT() asm volatile("cp.async.commit_group;")
#define CP_WAIT(n)  asm volatile("cp.async.wait_group %0;" :: "n"(n))

__device__ __forceinline__ void ldsm_x4(unsigned& r0, unsigned& r1, unsigned& r2, unsigned& r3, unsigned addr) {
    asm volatile("ldmatrix.sync.aligned.m8n8.x4.shared.b16 {%0,%1,%2,%3}, [%4];"
                 : "=r"(r0), "=r"(r1), "=r"(r2), "=r"(r3) : "r"(addr));
}
__device__ __forceinline__ void ldsm_x4t(unsigned& r0, unsigned& r1, unsigned& r2, unsigned& r3, unsigned addr) {
    asm volatile("ldmatrix.sync.aligned.m8n8.x4.trans.shared.b16 {%0,%1,%2,%3}, [%4];"
                 : "=r"(r0), "=r"(r1), "=r"(r2), "=r"(r3) : "r"(addr));
}

__device__ __forceinline__ void mma_f16(
    float& c0, float& c1, float& c2, float& c3,
    unsigned a0, unsigned a1, unsigned a2, unsigned a3,
    unsigned b0, unsigned b1)
{
    asm volatile(
        "mma.sync.aligned.m16n8k16.row.col.f32.f16.f16.f32 "
        "{%0,%1,%2,%3},{%4,%5,%6,%7},{%8,%9},{%0,%1,%2,%3};"
        : "+f"(c0), "+f"(c1), "+f"(c2), "+f"(c3)
        : "r"(a0), "r"(a1), "r"(a2), "r"(a3), "r"(b0), "r"(b1));
}

__device__ __forceinline__ unsigned f2key(float f) {
    unsigned b = __float_as_uint(f);
    return (b & 0x80000000u) ? ~b : (b | 0x80000000u);
}
__device__ __forceinline__ float key2f(unsigned u) {
    return __uint_as_float((u & 0x80000000u) ? (u & 0x7fffffffu) : ~u);
}

// ---------------- converter: fp32 -> fp16 for all GEMM operands ----------------
__global__ void __launch_bounds__(256) cvt_all(
    const float* __restrict__ Wq, const float* __restrict__ Wk,
    const float* __restrict__ Wv, const float* __restrict__ Wm,
    const float* __restrict__ q,  const float* __restrict__ k,
    const float* __restrict__ v,
    __half* Wqh, __half* Wkh, __half* Wvh, __half* Wmh,
    __half* qh, __half* kh, __half* vh)
{
    int bid = blockIdx.x;
    const float* src; __half* dst; int off;
    if      (bid < 512)  { src = Wq; dst = Wqh; off = bid; }
    else if (bid < 1024) { src = Wk; dst = Wkh; off = bid - 512; }
    else if (bid < 1536) { src = Wv; dst = Wvh; off = bid - 1024; }
    else if (bid < 2048) { src = Wm; dst = Wmh; off = bid - 1536; }
    else if (bid < 4096) { src = q;  dst = qh;  off = bid - 2048; }
    else if (bid < 6144) { src = k;  dst = kh;  off = bid - 4096; }
    else                 { src = v;  dst = vh;  off = bid - 6144; }
    size_t base = (size_t)off * 2048 + threadIdx.x * 8;
    float4 f0 = *(const float4*)&src[base];
    float4 f1 = *(const float4*)&src[base + 4];
    uint4 o = { f22h(f0.x, f0.y), f22h(f0.z, f0.w), f22h(f1.x, f1.y), f22h(f1.z, f1.w) };
    *(uint4*)&dst[base] = o;
}

// ---------------- fp16 GEMM: C = gate.*(A @ W) + bias ----------------
// BM=128, BN=128, BK=32, 256 threads = 8 warps (4m x 2n), warp tile 32x64.
// cp.async 3-stage pipeline, ldmatrix fragments.
constexpr int G_ASTH = 40;    // As stride halves (20 words: 20r%32 distinct)
constexpr int G_BSTH = 136;   // Bs stride halves (68 words: 4r%32 distinct)
constexpr int G_ASB  = 128 * G_ASTH * 2;   // 10240 B
constexpr int G_BSB  = 32 * G_BSTH * 2;    // 8704 B
constexpr int G_STAGE = G_ASB + G_BSB;     // 18944 B
constexpr int GEMM_SMEM = 3 * G_STAGE + 512;  // +gate

template <typename TC, bool GATED>
__global__ void __launch_bounds__(256) gemm_f16_kernel(
    const __half* __restrict__ A, const __half* __restrict__ W,
    const float* __restrict__ bias, TC* __restrict__ C,
    const float* __restrict__ colsum, const float* __restrict__ thr)
{
    extern __shared__ __align__(16) char smb[];
    const unsigned sb = smem_u32(smb);
    float* gate = (float*)(smb + 3 * G_STAGE);

    const int t    = threadIdx.x;
    const int w    = t >> 5;
    const int lane = t & 31;
    const int g    = lane >> 2;
    const int tg   = lane & 3;
    const int wm   = (w & 3) * 32;
    const int wn   = (w >> 2) * 64;

    const int m0 = blockIdx.y * 128;
    const int n0 = blockIdx.x * 128;

    // ldmatrix per-lane patterns
    const int arow = (lane & 7) + ((lane >> 3) & 1) * 8;
    const int acol = (lane >> 4) * 8;
    const int brow = lane & 7;
    const int bseg = (lane >> 3) * 8;
    (void)brow; (void)bseg;

    if (GATED && t < 128)
        gate[t] = ((colsum[m0 + t] - thr[m0 + t]) > 0.f) ? 1.f : 0.f;

    // staging: per thread 2 A chunks + 2 W chunks (16B each)
    const int a_row0 = t >> 2;            // + 64
    const int a_seg  = (t & 3) * 8;
    const int w_row0 = t >> 4;            // + 16
    const int w_seg  = (t & 15) * 8;

    auto stage = [&](int s, int kt) {
        const int k0 = kt * 32;
        unsigned as = sb + s * G_STAGE;
        unsigned bs = sb + s * G_STAGE + G_ASB;
        cp16(as + (a_row0 * G_ASTH + a_seg) * 2,        &A[(size_t)(m0 + a_row0) * GK + k0 + a_seg]);
        cp16(as + ((a_row0 + 64) * G_ASTH + a_seg) * 2, &A[(size_t)(m0 + a_row0 + 64) * GK + k0 + a_seg]);
        cp16(bs + (w_row0 * G_BSTH + w_seg) * 2,        &W[(size_t)(k0 + w_row0) * GN + n0 + w_seg]);
        cp16(bs + ((w_row0 + 16) * G_BSTH + w_seg) * 2, &W[(size_t)(k0 + w_row0 + 16) * GN + n0 + w_seg]);
    };

    constexpr int NT = GK / 32;   // 32
    stage(0, 0); CP_COMMIT();
    stage(1, 1); CP_COMMIT();

    float c[2][8][4] = {};

    for (int kt = 0; kt < NT; kt++) {
        CP_WAIT(1);
        __syncthreads();
        if (kt + 2 < NT) stage((kt + 2) % 3, kt + 2);
        CP_COMMIT();

        const unsigned as = sb + (kt % 3) * G_STAGE;
        const unsigned bs = as + G_ASB;

        #pragma unroll
        for (int kb = 0; kb < 2; kb++) {
            unsigned a[2][4];
            #pragma unroll
            for (int mt = 0; mt < 2; mt++)
                ldsm_x4(a[mt][0], a[mt][1], a[mt][2], a[mt][3],
                        as + ((wm + mt * 16 + arow) * G_ASTH + kb * 16 + acol) * 2);
            unsigned bf[4][4];
            #pragma unroll
            for (int nn = 0; nn < 4; nn++)
                ldsm_x4t(bf[nn][0], bf[nn][1], bf[nn][2], bf[nn][3],
                         bs + ((kb * 16 + arow) * G_BSTH + wn + nn * 16 + acol) * 2);
            #pragma unroll
            for (int mt = 0; mt < 2; mt++)
                #pragma unroll
                for (int ng = 0; ng < 8; ng++)
                    mma_f16(c[mt][ng][0], c[mt][ng][1], c[mt][ng][2], c[mt][ng][3],
                            a[mt][0], a[mt][1], a[mt][2], a[mt][3],
                            bf[ng >> 1][(ng & 1) * 2], bf[ng >> 1][(ng & 1) * 2 + 1]);
        }
        __syncthreads();
    }

    #pragma unroll
    for (int mt = 0; mt < 2; mt++) {
        const int r = wm + mt * 16 + g;
        const float gv0 = GATED ? gate[r]     : 1.f;
        const float gv1 = GATED ? gate[r + 8] : 1.f;
        #pragma unroll
        for (int ng = 0; ng < 8; ng++) {
            const int col = n0 + wn + ng * 8 + 2 * tg;
            float2 bb = *(const float2*)&bias[col];
            float o00 = c[mt][ng][0] * gv0 + bb.x;
            float o01 = c[mt][ng][1] * gv0 + bb.y;
            float o10 = c[mt][ng][2] * gv1 + bb.x;
            float o11 = c[mt][ng][3] * gv1 + bb.y;
            if constexpr (sizeof(TC) == 2) {
                *(unsigned*)&C[(size_t)(m0 + r)     * GN + col] = f22h(o00, o01);
                *(unsigned*)&C[(size_t)(m0 + r + 8) * GN + col] = f22h(o10, o11);
            } else {
                *(float2*)&C[(size_t)(m0 + r)     * GN + col] = make_float2(o00, o01);
                *(float2*)&C[(size_t)(m0 + r + 8) * GN + col] = make_float2(o10, o11);
            }
        }
    }
}

// ---------------- threshold (also zeroes colsum) ----------------
__global__ void __launch_bounds__(128) threshold_kernel(
    const __half* __restrict__ qp, const __half* __restrict__ kp,
    const float* __restrict__ Wt, const float* __restrict__ bt,
    float* __restrict__ thr, float* __restrict__ colsum)
{
    __shared__ float red[4];
    const int row = blockIdx.x;
    const int t = threadIdx.x;
    const __half* qr = qp + (size_t)row * Hh;
    const __half* kr = kp + (size_t)row * Hh;
    float acc = 0.f;
    for (int i = t; i < Hh; i += 128)
        acc += __half2float(qr[i]) * __half2float(kr[i]) * Wt[i];
    #pragma unroll
    for (int o = 16; o; o >>= 1) acc += __shfl_xor_sync(0xffffffffu, acc, o);
    if ((t & 31) == 0) red[t >> 5] = acc;
    __syncthreads();
    if (t == 0) {
        thr[row] = red[0] + red[1] + red[2] + red[3] + bt[0];
        colsum[row] = 0.f;
    }
}

// ---------------- attention mega-kernel: QT=32, fp16 S strip ----------------
constexpr int QT  = 32;
constexpr int KT  = 128;
constexpr int NKT = Ll / KT;        // 16

constexpr int SSTH  = 2056;         // S stride halves (1028 words: 4r distinct)
constexpr int QSTH  = 72;
constexpr int KVSTH = 72;           // 36 words: 4r distinct
constexpr int KVBUF = KT * KVSTH;   // halves per stage

constexpr int SH_OFF = 0;
constexpr int QH_OFF = QT * SSTH;                  // 65792 halves
constexpr int KV_OFF = QH_OFF + QT * QSTH;         // 68096
constexpr int FL_OFF = KV_OFF + 3 * KVBUF;         // 95744 halves -> byte 191488
constexpr int ATTN_SMEM = FL_OFF * 2 + 64 * 4;     // + rowmax[32] + invl[32]

// fp32 reduction slabs over the (dead) S region
constexpr int RROW = 68;            // floats per row
constexpr int RSLAB = 32 * RROW;    // 2176 floats per slab

__global__ void __launch_bounds__(512, 1) attn_kernel(
    const __half* __restrict__ qp, const __half* __restrict__ kp,
    const __half* __restrict__ vp, const unsigned char* __restrict__ mask,
    __half* __restrict__ atted, float* __restrict__ colsum)
{
    extern __shared__ __align__(16) char smb[];
    __half* Sh = (__half*)smb;
    __half* Qh = (__half*)smb + QH_OFF;
    unsigned* rowmaxU = (unsigned*)(smb + FL_OFF * 2);
    float* invl = (float*)(smb + FL_OFF * 2 + 128);
    const unsigned sb   = smem_u32(smb);
    const unsigned shS  = sb;
    const unsigned shQ  = sb + QH_OFF * 2;
    const unsigned shKV = sb + KV_OFF * 2;

    const int t    = threadIdx.x;
    const int w    = t >> 5;
    const int lane = t & 31;
    const int g    = lane >> 2;
    const int tg   = lane & 3;

    const int bx = blockIdx.x;
    const int qt = bx & 63;
    const int h  = (bx >> 6) & 15;
    const int b  = bx >> 10;
    const int q0 = qt * QT;
    const int hd = h * DHd;

    const int arow = (lane & 7) + ((lane >> 3) & 1) * 8;
    const int acol = (lane >> 4) * 8;
    const int brow = lane & 7;
    const int bseg = (lane >> 3) * 8;

    const __half* kbase = kp + (size_t)(b * Ll) * Hh + hd;
    const __half* vbase = vp + (size_t)(b * Ll) * Hh + hd;

    // staging: 1024 16B-chunks per 128x64 tile, 2 per thread
    const int s_row0 = t >> 3;          // + 64
    const int s_c8   = (t & 7) * 8;

    auto stage_tile = [&](int s, const __half* base, int tile) {
        const __half* src = base + (size_t)(tile * KT) * Hh;
        unsigned dst = shKV + s * (KVBUF * 2);
        cp16(dst + (s_row0 * KVSTH + s_c8) * 2,        &src[(size_t)s_row0 * Hh + s_c8]);
        cp16(dst + ((s_row0 + 64) * KVSTH + s_c8) * 2, &src[(size_t)(s_row0 + 64) * Hh + s_c8]);
    };

    // ---- init rowmax, stage Q, prologue K tiles ----
    if (t < 32) rowmaxU[t] = 0u;
    if (t < 256) {
        int r = t >> 3, c8 = (t & 7) * 8;
        *(uint4*)&Qh[r * QSTH + c8] =
            *(const uint4*)&qp[(size_t)(b * Ll + q0 + r) * Hh + hd + c8];
    }
    stage_tile(0, kbase, 0); CP_COMMIT();
    stage_tile(1, kbase, 1); CP_COMMIT();
    __syncthreads();

    // ---- Q fragments: aq[mt][kb][4] ----
    unsigned aq[2][4][4];
    #pragma unroll
    for (int mt = 0; mt < 2; mt++)
        #pragma unroll
        for (int kb = 0; kb < 4; kb++)
            ldsm_x4(aq[mt][kb][0], aq[mt][kb][1], aq[mt][kb][2], aq[mt][kb][3],
                    shQ + ((mt * 16 + arow) * QSTH + kb * 16 + acol) * 2);

    const int n0 = (w & 7) * 8 + (w >> 3) * 64;

    // ---- QK: S = Q K^T / 8, running row max ----
    float lm[4] = { -1e30f, -1e30f, -1e30f, -1e30f };

    for (int kt = 0; kt < NKT; kt++) {
        CP_WAIT(1);
        __syncthreads();
        if (kt + 2 < NKT) stage_tile((kt + 2) % 3, kbase, kt + 2);
        CP_COMMIT();

        const unsigned kvb = shKV + (kt % 3) * (KVBUF * 2);
        unsigned bk[4][2];
        {
            unsigned r0, r1, r2, r3;
            ldsm_x4(r0, r1, r2, r3, kvb + ((n0 + brow) * KVSTH + bseg) * 2);
            bk[0][0] = r0; bk[0][1] = r1; bk[1][0] = r2; bk[1][1] = r3;
            ldsm_x4(r0, r1, r2, r3, kvb + ((n0 + brow) * KVSTH + 32 + bseg) * 2);
            bk[2][0] = r0; bk[2][1] = r1; bk[3][0] = r2; bk[3][1] = r3;
        }

        float c[2][4] = {};
        #pragma unroll
        for (int mt = 0; mt < 2; mt++)
            #pragma unroll
            for (int kb = 0; kb < 4; kb++)
                mma_f16(c[mt][0], c[mt][1], c[mt][2], c[mt][3],
                        aq[mt][kb][0], aq[mt][kb][1], aq[mt][kb][2], aq[mt][kb][3],
                        bk[kb][0], bk[kb][1]);

        const int key = kt * KT + n0 + 2 * tg;
        const unsigned char m0 = mask[b * Ll + key];
        const unsigned char m1 = mask[b * Ll + key + 1];
        #pragma unroll
        for (int mt = 0; mt < 2; mt++) {
            float s00 = m0 ? -1e9f : c[mt][0] * 0.125f;
            float s01 = m1 ? -1e9f : c[mt][1] * 0.125f;
            float s10 = m0 ? -1e9f : c[mt][2] * 0.125f;
            float s11 = m1 ? -1e9f : c[mt][3] * 0.125f;
            lm[mt * 2]     = fmaxf(lm[mt * 2],     fmaxf(s00, s01));
            lm[mt * 2 + 1] = fmaxf(lm[mt * 2 + 1], fmaxf(s10, s11));
            *(unsigned*)&Sh[(mt * 16 + g)     * SSTH + key] = f22h(s00, s01);
            *(unsigned*)&Sh[(mt * 16 + g + 8) * SSTH + key] = f22h(s10, s11);
        }
        __syncthreads();
    }

    // ---- row max reduce ----
    #pragma unroll
    for (int i = 0; i < 4; i++) {
        lm[i] = fmaxf(lm[i], __shfl_xor_sync(0xffffffffu, lm[i], 1));
        lm[i] = fmaxf(lm[i], __shfl_xor_sync(0xffffffffu, lm[i], 2));
    }
    if (tg == 0) {
        atomicMax(&rowmaxU[g],      f2key(lm[0]));
        atomicMax(&rowmaxU[g + 8],  f2key(lm[1]));
        atomicMax(&rowmaxU[g + 16], f2key(lm[2]));
        atomicMax(&rowmaxU[g + 24], f2key(lm[3]));
    }
    __syncthreads();

    // prologue V tiles (overlaps with exp/colsum)
    stage_tile(0, vbase, 0); CP_COMMIT();
    stage_tile(1, vbase, 1); CP_COMMIT();

    // ---- exp in place (half), row sums: warp w owns rows 2w, 2w+1 ----
    #pragma unroll
    for (int rr = 0; rr < 2; rr++) {
        const int r = 2 * w + rr;
        const float m = key2f(rowmaxU[r]);
        __half* Sr = Sh + r * SSTH;
        float sum = 0.f;
        #pragma unroll 4
        for (int i = 0; i < 32; i++) {
            const int cc = i * 64 + 2 * lane;
            __half2 hv = *(__half2*)&Sr[cc];
            float e0 = __expf(__half2float(hv.x) - m);
            float e1 = __expf(__half2float(hv.y) - m);
            sum += e0 + e1;
            *(unsigned*)&Sr[cc] = f22h(e0, e1);
        }
        #pragma unroll
        for (int o = 16; o; o >>= 1) sum += __shfl_xor_sync(0xffffffffu, sum, o);
        if (lane == 0) invl[r] = 1.f / sum;
    }
    __syncthreads();

    // ---- colsum ----
    {
        float il[QT];
        #pragma unroll
        for (int r = 0; r < QT; r++) il[r] = invl[r];
        for (int k2 = 2 * t; k2 < Ll; k2 += 1024) {
            float a0 = 0.f, a1 = 0.f;
            #pragma unroll
            for (int r = 0; r < QT; r++) {
                __half2 p = *(__half2*)&Sh[r * SSTH + k2];
                a0 += __half2float(p.x) * il[r];
                a1 += __half2float(p.y) * il[r];
            }
            atomicAdd(&colsum[b * Ll + k2],     a0);
            atomicAdd(&colsum[b * Ll + k2 + 1], a1);
        }
    }

    // ---- PV: warp = key-slice (w&7)*16 x d-half (w>>3)*32 ----
    const int sk = (w & 7) * 16;
    const int dh = (w >> 3) * 32;
    float c[2][4][4] = {};

    for (int vt = 0; vt < NKT; vt++) {
        CP_WAIT(1);
        __syncthreads();
        if (vt + 2 < NKT) stage_tile((vt + 2) % 3, vbase, vt + 2);
        CP_COMMIT();

        const unsigned kvb = shKV + (vt % 3) * (KVBUF * 2);

        unsigned ap[2][4];
        #pragma unroll
        for (int mt = 0; mt < 2; mt++)
            ldsm_x4(ap[mt][0], ap[mt][1], ap[mt][2], ap[mt][3],
                    shS + ((mt * 16 + arow) * SSTH + vt * KT + sk + acol) * 2);

        unsigned bv[2][4];
        #pragma unroll
        for (int nn = 0; nn < 2; nn++)
            ldsm_x4t(bv[nn][0], bv[nn][1], bv[nn][2], bv[nn][3],
                     kvb + ((sk + arow) * KVSTH + dh + nn * 16 + acol) * 2);

        #pragma unroll
        for (int mt = 0; mt < 2; mt++)
            #pragma unroll
            for (int ng = 0; ng < 4; ng++)
                mma_f16(c[mt][ng][0], c[mt][ng][1], c[mt][ng][2], c[mt][ng][3],
                        ap[mt][0], ap[mt][1], ap[mt][2], ap[mt][3],
                        bv[ng >> 1][(ng & 1) * 2], bv[ng >> 1][(ng & 1) * 2 + 1]);
    }
    __syncthreads();

    // ---- 8-way reduction of key-slice partials (fp32 slabs over S region) ----
    float* R = (float*)smb;
    const int slab = w & 7;
    #pragma unroll
    for (int mt = 0; mt < 2; mt++)
        #pragma unroll
        for (int ng = 0; ng < 4; ng++) {
            const int col = dh + ng * 8 + 2 * tg;
            *(float2*)&R[slab * RSLAB + (mt * 16 + g)     * RROW + col] = make_float2(c[mt][ng][0], c[mt][ng][1]);
            *(float2*)&R[slab * RSLAB + (mt * 16 + g + 8) * RROW + col] = make_float2(c[mt][ng][2], c[mt][ng][3]);
        }
    __syncthreads();

    for (int id = t; id < QT * DHd / 2; id += 512) {
        const int r  = id >> 5;
        const int d  = (id & 31) * 2;
        float s0 = 0.f, s1 = 0.f;
        #pragma unroll
        for (int sl = 0; sl < 8; sl++) {
            s0 += R[sl * RSLAB + r * RROW + d];
            s1 += R[sl * RSLAB + r * RROW + d + 1];
        }
        const float il = invl[r];
        *(unsigned*)&atted[(size_t)(b * Ll + q0 + r) * Hh + hd + d] = f22h(s0 * il, s1 * il);
    }
}

// ---------------- launch ----------------
extern "C" void kernel_launch(void* const* d_in, const int* in_sizes, int n_in,
                              void* d_out, int out_size)
{
    const float* v  = (const float*)d_in[0];
    const float* k  = (const float*)d_in[1];
    const float* q  = (const float*)d_in[2];
    const unsigned char* mask = (const unsigned char*)d_in[3];
    const float* Wv = (const float*)d_in[4];
    const float* bv = (const float*)d_in[5];
    const float* Wk = (const float*)d_in[6];
    const float* bk = (const float*)d_in[7];
    const float* Wq = (const float*)d_in[8];
    const float* bq = (const float*)d_in[9];
    const float* Wt = (const float*)d_in[10];
    const float* bt = (const float*)d_in[11];
    const float* Wm = (const float*)d_in[12];
    const float* bm = (const float*)d_in[13];
    float* out = (float*)d_out;

    __half *qh, *kh, *vh, *Wqh, *Wkh, *Wvh, *Wmh, *qp, *kp, *vp, *atted;
    float *thr, *colsum;
    cudaGetSymbolAddress((void**)&qh,  g_qh);
    cudaGetSymbolAddress((void**)&kh,  g_kh);
    cudaGetSymbolAddress((void**)&vh,  g_vh);
    cudaGetSymbolAddress((void**)&Wqh, g_Wqh);
    cudaGetSymbolAddress((void**)&Wkh, g_Wkh);
    cudaGetSymbolAddress((void**)&Wvh, g_Wvh);
    cudaGetSymbolAddress((void**)&Wmh, g_Wmh);
    cudaGetSymbolAddress((void**)&qp,  g_qp);
    cudaGetSymbolAddress((void**)&kp,  g_kp);
    cudaGetSymbolAddress((void**)&vp,  g_vp);
    cudaGetSymbolAddress((void**)&atted, g_atted);
    cudaGetSymbolAddress((void**)&thr,   g_thr);
    cudaGetSymbolAddress((void**)&colsum, g_colsum);

    cudaFuncSetAttribute(attn_kernel, cudaFuncAttributeMaxDynamicSharedMemorySize, ATTN_SMEM);
    cudaFuncSetAttribute(gemm_f16_kernel<__half, false>, cudaFuncAttributeMaxDynamicSharedMemorySize, GEMM_SMEM);
    cudaFuncSetAttribute(gemm_f16_kernel<float, true>,   cudaFuncAttributeMaxDynamicSharedMemorySize, GEMM_SMEM);

    cvt_all<<<8192, 256>>>(Wq, Wk, Wv, Wm, q, k, v, Wqh, Wkh, Wvh, Wmh, qh, kh, vh);

    dim3 gg(GN / 128, GM / 128);
    gemm_f16_kernel<__half, false><<<gg, 256, GEMM_SMEM>>>(qh, Wqh, bq, qp, nullptr, nullptr);
    gemm_f16_kernel<__half, false><<<gg, 256, GEMM_SMEM>>>(kh, Wkh, bk, kp, nullptr, nullptr);
    gemm_f16_kernel<__half, false><<<gg, 256, GEMM_SMEM>>>(vh, Wvh, bv, vp, nullptr, nullptr);

    threshold_kernel<<<GM, 128>>>(qp, kp, Wt, bt, thr, colsum);

    attn_kernel<<<Bb * NHh * (Ll / QT), 512, ATTN_SMEM>>>(qp, kp, vp, mask, atted, colsum);

    gemm_f16_kernel<float, true><<<gg, 256, GEMM_SMEM>>>(atted, Wmh, bm, out, colsum, thr);
}

// round 8
// speedup vs baseline: 10.1104x; 1.0650x over previous
#include <cuda_runtime.h>
#include <cuda_fp16.h>

// Problem constants
constexpr int Bb  = 2;
constexpr int Ll  = 2048;
constexpr int Hh  = 1024;
constexpr int NHh = 16;
constexpr int DHd = 64;

constexpr int GM = Bb * Ll;   // 4096
constexpr int GN = Hh;        // 1024
constexpr int GK = Hh;        // 1024

// ---------------- device scratch ----------------
__device__ __half g_qh[GM * Hh];
__device__ __half g_kh[GM * Hh];
__device__ __half g_vh[GM * Hh];
__device__ __half g_Wqh[Hh * Hh];
__device__ __half g_Wkh[Hh * Hh];
__device__ __half g_Wvh[Hh * Hh];
__device__ __half g_Wmh[Hh * Hh];
__device__ __half g_qp[GM * Hh];
__device__ __half g_kp[GM * Hh];
__device__ __half g_vp[GM * Hh];
__device__ __half g_atted[GM * Hh];
__device__ float  g_thr[GM];
__device__ float  g_colsum[GM];

// ---------------- helpers ----------------
__device__ __forceinline__ unsigned f22h(float a, float b) {
    __half2 h = __floats2half2_rn(a, b);
    return *(unsigned*)&h;
}

__device__ __forceinline__ unsigned smem_u32(const void* p) {
    unsigned a;
    asm("{ .reg .u64 t; cvta.to.shared.u64 t, %1; cvt.u32.u64 %0, t; }" : "=r"(a) : "l"(p));
    return a;
}

__device__ __forceinline__ void cp16(unsigned dst, const void* src) {
    asm volatile("cp.async.cg.shared.global [%0], [%1], 16;" :: "r"(dst), "l"(src));
}
#define CP_COMMIT() asm volatile("cp.async.commit_group;")
#define CP_WAIT(n)  asm volatile("cp.async.wait_group %0;" :: "n"(n))

__device__ __forceinline__ void ldsm_x4(unsigned& r0, unsigned& r1, unsigned& r2, unsigned& r3, unsigned addr) {
    asm volatile("ldmatrix.sync.aligned.m8n8.x4.shared.b16 {%0,%1,%2,%3}, [%4];"
                 : "=r"(r0), "=r"(r1), "=r"(r2), "=r"(r3) : "r"(addr));
}
__device__ __forceinline__ void ldsm_x4t(unsigned& r0, unsigned& r1, unsigned& r2, unsigned& r3, unsigned addr) {
    asm volatile("ldmatrix.sync.aligned.m8n8.x4.trans.shared.b16 {%0,%1,%2,%3}, [%4];"
                 : "=r"(r0), "=r"(r1), "=r"(r2), "=r"(r3) : "r"(addr));
}

__device__ __forceinline__ void mma_f16(
    float& c0, float& c1, float& c2, float& c3,
    unsigned a0, unsigned a1, unsigned a2, unsigned a3,
    unsigned b0, unsigned b1)
{
    asm volatile(
        "mma.sync.aligned.m16n8k16.row.col.f32.f16.f16.f32 "
        "{%0,%1,%2,%3},{%4,%5,%6,%7},{%8,%9},{%0,%1,%2,%3};"
        : "+f"(c0), "+f"(c1), "+f"(c2), "+f"(c3)
        : "r"(a0), "r"(a1), "r"(a2), "r"(a3), "r"(b0), "r"(b1));
}

__device__ __forceinline__ unsigned f2key(float f) {
    unsigned b = __float_as_uint(f);
    return (b & 0x80000000u) ? ~b : (b | 0x80000000u);
}
__device__ __forceinline__ float key2f(unsigned u) {
    return __uint_as_float((u & 0x80000000u) ? (u & 0x7fffffffu) : ~u);
}

// ---------------- converter: fp32 -> fp16 for all GEMM operands ----------------
__global__ void __launch_bounds__(256) cvt_all(
    const float* __restrict__ Wq, const float* __restrict__ Wk,
    const float* __restrict__ Wv, const float* __restrict__ Wm,
    const float* __restrict__ q,  const float* __restrict__ k,
    const float* __restrict__ v,
    __half* Wqh, __half* Wkh, __half* Wvh, __half* Wmh,
    __half* qh, __half* kh, __half* vh)
{
    int bid = blockIdx.x;
    const float* src; __half* dst; int off;
    if      (bid < 512)  { src = Wq; dst = Wqh; off = bid; }
    else if (bid < 1024) { src = Wk; dst = Wkh; off = bid - 512; }
    else if (bid < 1536) { src = Wv; dst = Wvh; off = bid - 1024; }
    else if (bid < 2048) { src = Wm; dst = Wmh; off = bid - 1536; }
    else if (bid < 4096) { src = q;  dst = qh;  off = bid - 2048; }
    else if (bid < 6144) { src = k;  dst = kh;  off = bid - 4096; }
    else                 { src = v;  dst = vh;  off = bid - 6144; }
    size_t base = (size_t)off * 2048 + threadIdx.x * 8;
    float4 f0 = *(const float4*)&src[base];
    float4 f1 = *(const float4*)&src[base + 4];
    uint4 o = { f22h(f0.x, f0.y), f22h(f0.z, f0.w), f22h(f1.x, f1.y), f22h(f1.z, f1.w) };
    *(uint4*)&dst[base] = o;
}

// ---------------- fp16 GEMM v3: C = gate.*(A @ W) + bias ----------------
// BM=128, BN=128, BK=32, 512 threads = 16 warps (4m x 4n), warp tile 32x32.
// cp.async 3-stage pipeline, ldmatrix fragments, fused z-batch.
constexpr int G_ASTH = 40;    // As stride halves
constexpr int G_BSTH = 136;   // Bs stride halves
constexpr int G_ASB  = 128 * G_ASTH * 2;   // 10240 B
constexpr int G_BSB  = 32 * G_BSTH * 2;    // 8704 B
constexpr int G_STAGE = G_ASB + G_BSB;     // 18944 B
constexpr int GEMM_SMEM = 3 * G_STAGE;     // 56832 B

template <typename TC, bool GATED>
__global__ void __launch_bounds__(512, 2) gemm_f16_kernel(
    const __half* __restrict__ A0, const __half* __restrict__ A1, const __half* __restrict__ A2,
    const __half* __restrict__ W0, const __half* __restrict__ W1, const __half* __restrict__ W2,
    const float* __restrict__ b0p, const float* __restrict__ b1p, const float* __restrict__ b2p,
    TC* __restrict__ C0, TC* __restrict__ C1, TC* __restrict__ C2,
    const float* __restrict__ colsum, const float* __restrict__ thr)
{
    extern __shared__ __align__(16) char smb[];
    const unsigned sb = smem_u32(smb);

    const int z = blockIdx.z;
    const __half* A = (z == 0) ? A0 : (z == 1) ? A1 : A2;
    const __half* W = (z == 0) ? W0 : (z == 1) ? W1 : W2;
    const float* bias = (z == 0) ? b0p : (z == 1) ? b1p : b2p;
    TC* C = (z == 0) ? C0 : (z == 1) ? C1 : C2;

    const int t    = threadIdx.x;
    const int w    = t >> 5;
    const int lane = t & 31;
    const int g    = lane >> 2;
    const int tg   = lane & 3;
    const int wm   = (w & 3) * 32;
    const int wn   = (w >> 2) * 32;

    const int m0 = blockIdx.y * 128;
    const int n0 = blockIdx.x * 128;

    // ldmatrix per-lane patterns
    const int arow = (lane & 7) + ((lane >> 3) & 1) * 8;
    const int acol = (lane >> 4) * 8;

    // staging: 1 A chunk + 1 W chunk per thread (16B each)
    const int a_row = t >> 2;             // 0..127
    const int a_seg = (t & 3) * 8;
    const int w_row = t >> 4;             // 0..31
    const int w_seg = (t & 15) * 8;

    auto stage = [&](int s, int kt) {
        const int k0 = kt * 32;
        unsigned as = sb + s * G_STAGE;
        unsigned bs = as + G_ASB;
        cp16(as + (a_row * G_ASTH + a_seg) * 2, &A[(size_t)(m0 + a_row) * GK + k0 + a_seg]);
        cp16(bs + (w_row * G_BSTH + w_seg) * 2, &W[(size_t)(k0 + w_row) * GN + n0 + w_seg]);
    };

    constexpr int NT = GK / 32;   // 32
    stage(0, 0); CP_COMMIT();
    stage(1, 1); CP_COMMIT();

    float c[2][4][4] = {};

    for (int kt = 0; kt < NT; kt++) {
        CP_WAIT(1);
        __syncthreads();
        if (kt + 2 < NT) stage((kt + 2) % 3, kt + 2);
        CP_COMMIT();

        const unsigned as = sb + (kt % 3) * G_STAGE;
        const unsigned bs = as + G_ASB;

        #pragma unroll
        for (int kb = 0; kb < 2; kb++) {
            unsigned a[2][4];
            #pragma unroll
            for (int mt = 0; mt < 2; mt++)
                ldsm_x4(a[mt][0], a[mt][1], a[mt][2], a[mt][3],
                        as + ((wm + mt * 16 + arow) * G_ASTH + kb * 16 + acol) * 2);
            unsigned bf[2][4];
            #pragma unroll
            for (int nn = 0; nn < 2; nn++)
                ldsm_x4t(bf[nn][0], bf[nn][1], bf[nn][2], bf[nn][3],
                         bs + ((kb * 16 + arow) * G_BSTH + wn + nn * 16 + acol) * 2);
            #pragma unroll
            for (int mt = 0; mt < 2; mt++)
                #pragma unroll
                for (int ng = 0; ng < 4; ng++)
                    mma_f16(c[mt][ng][0], c[mt][ng][1], c[mt][ng][2], c[mt][ng][3],
                            a[mt][0], a[mt][1], a[mt][2], a[mt][3],
                            bf[ng >> 1][(ng & 1) * 2], bf[ng >> 1][(ng & 1) * 2 + 1]);
        }
        __syncthreads();
    }

    #pragma unroll
    for (int mt = 0; mt < 2; mt++) {
        const int r = m0 + wm + mt * 16 + g;
        float gv0 = 1.f, gv1 = 1.f;
        if (GATED) {
            gv0 = ((colsum[r]     - thr[r])     > 0.f) ? 1.f : 0.f;
            gv1 = ((colsum[r + 8] - thr[r + 8]) > 0.f) ? 1.f : 0.f;
        }
        #pragma unroll
        for (int ng = 0; ng < 4; ng++) {
            const int col = n0 + wn + ng * 8 + 2 * tg;
            float2 bb = *(const float2*)&bias[col];
            float o00 = c[mt][ng][0] * gv0 + bb.x;
            float o01 = c[mt][ng][1] * gv0 + bb.y;
            float o10 = c[mt][ng][2] * gv1 + bb.x;
            float o11 = c[mt][ng][3] * gv1 + bb.y;
            if constexpr (sizeof(TC) == 2) {
                *(unsigned*)&C[(size_t)r * GN + col]       = f22h(o00, o01);
                *(unsigned*)&C[(size_t)(r + 8) * GN + col] = f22h(o10, o11);
            } else {
                *(float2*)&C[(size_t)r * GN + col]       = make_float2(o00, o01);
                *(float2*)&C[(size_t)(r + 8) * GN + col] = make_float2(o10, o11);
            }
        }
    }
}

// ---------------- threshold (also zeroes colsum) ----------------
__global__ void __launch_bounds__(128) threshold_kernel(
    const __half* __restrict__ qp, const __half* __restrict__ kp,
    const float* __restrict__ Wt, const float* __restrict__ bt,
    float* __restrict__ thr, float* __restrict__ colsum)
{
    __shared__ float red[4];
    const int row = blockIdx.x;
    const int t = threadIdx.x;
    const __half* qr = qp + (size_t)row * Hh;
    const __half* kr = kp + (size_t)row * Hh;
    float acc = 0.f;
    for (int i = t; i < Hh; i += 128)
        acc += __half2float(qr[i]) * __half2float(kr[i]) * Wt[i];
    #pragma unroll
    for (int o = 16; o; o >>= 1) acc += __shfl_xor_sync(0xffffffffu, acc, o);
    if ((t & 31) == 0) red[t >> 5] = acc;
    __syncthreads();
    if (t == 0) {
        thr[row] = red[0] + red[1] + red[2] + red[3] + bt[0];
        colsum[row] = 0.f;
    }
}

// ---------------- attention mega-kernel: QT=32, fp16 S strip ----------------
constexpr int QT  = 32;
constexpr int KT  = 128;
constexpr int NKT = Ll / KT;        // 16

constexpr int SSTH  = 2056;
constexpr int QSTH  = 72;
constexpr int KVSTH = 72;
constexpr int KVBUF = KT * KVSTH;

constexpr int QH_OFF = QT * SSTH;
constexpr int KV_OFF = QH_OFF + QT * QSTH;
constexpr int FL_OFF = KV_OFF + 3 * KVBUF;
constexpr int ATTN_SMEM = FL_OFF * 2 + 64 * 4;

constexpr int RROW = 68;
constexpr int RSLAB = 32 * RROW;

__global__ void __launch_bounds__(512, 1) attn_kernel(
    const __half* __restrict__ qp, const __half* __restrict__ kp,
    const __half* __restrict__ vp, const unsigned char* __restrict__ mask,
    __half* __restrict__ atted, float* __restrict__ colsum)
{
    extern __shared__ __align__(16) char smb[];
    __half* Sh = (__half*)smb;
    __half* Qh = (__half*)smb + QH_OFF;
    unsigned* rowmaxU = (unsigned*)(smb + FL_OFF * 2);
    float* invl = (float*)(smb + FL_OFF * 2 + 128);
    const unsigned sb   = smem_u32(smb);
    const unsigned shS  = sb;
    const unsigned shQ  = sb + QH_OFF * 2;
    const unsigned shKV = sb + KV_OFF * 2;

    const int t    = threadIdx.x;
    const int w    = t >> 5;
    const int lane = t & 31;
    const int g    = lane >> 2;
    const int tg   = lane & 3;

    const int bx = blockIdx.x;
    const int qt = bx & 63;
    const int h  = (bx >> 6) & 15;
    const int b  = bx >> 10;
    const int q0 = qt * QT;
    const int hd = h * DHd;

    const int arow = (lane & 7) + ((lane >> 3) & 1) * 8;
    const int acol = (lane >> 4) * 8;
    const int brow = lane & 7;
    const int bseg = (lane >> 3) * 8;

    const __half* kbase = kp + (size_t)(b * Ll) * Hh + hd;
    const __half* vbase = vp + (size_t)(b * Ll) * Hh + hd;

    const int s_row0 = t >> 3;
    const int s_c8   = (t & 7) * 8;

    auto stage_tile = [&](int s, const __half* base, int tile) {
        const __half* src = base + (size_t)(tile * KT) * Hh;
        unsigned dst = shKV + s * (KVBUF * 2);
        cp16(dst + (s_row0 * KVSTH + s_c8) * 2,        &src[(size_t)s_row0 * Hh + s_c8]);
        cp16(dst + ((s_row0 + 64) * KVSTH + s_c8) * 2, &src[(size_t)(s_row0 + 64) * Hh + s_c8]);
    };

    if (t < 32) rowmaxU[t] = 0u;
    if (t < 256) {
        int r = t >> 3, c8 = (t & 7) * 8;
        *(uint4*)&Qh[r * QSTH + c8] =
            *(const uint4*)&qp[(size_t)(b * Ll + q0 + r) * Hh + hd + c8];
    }
    stage_tile(0, kbase, 0); CP_COMMIT();
    stage_tile(1, kbase, 1); CP_COMMIT();
    __syncthreads();

    unsigned aq[2][4][4];
    #pragma unroll
    for (int mt = 0; mt < 2; mt++)
        #pragma unroll
        for (int kb = 0; kb < 4; kb++)
            ldsm_x4(aq[mt][kb][0], aq[mt][kb][1], aq[mt][kb][2], aq[mt][kb][3],
                    shQ + ((mt * 16 + arow) * QSTH + kb * 16 + acol) * 2);

    const int n0 = (w & 7) * 8 + (w >> 3) * 64;

    float lm[4] = { -1e30f, -1e30f, -1e30f, -1e30f };

    for (int kt = 0; kt < NKT; kt++) {
        CP_WAIT(1);
        __syncthreads();
        if (kt + 2 < NKT) stage_tile((kt + 2) % 3, kbase, kt + 2);
        CP_COMMIT();

        const unsigned kvb = shKV + (kt % 3) * (KVBUF * 2);
        unsigned bk[4][2];
        {
            unsigned r0, r1, r2, r3;
            ldsm_x4(r0, r1, r2, r3, kvb + ((n0 + brow) * KVSTH + bseg) * 2);
            bk[0][0] = r0; bk[0][1] = r1; bk[1][0] = r2; bk[1][1] = r3;
            ldsm_x4(r0, r1, r2, r3, kvb + ((n0 + brow) * KVSTH + 32 + bseg) * 2);
            bk[2][0] = r0; bk[2][1] = r1; bk[3][0] = r2; bk[3][1] = r3;
        }

        float c[2][4] = {};
        #pragma unroll
        for (int mt = 0; mt < 2; mt++)
            #pragma unroll
            for (int kb = 0; kb < 4; kb++)
                mma_f16(c[mt][0], c[mt][1], c[mt][2], c[mt][3],
                        aq[mt][kb][0], aq[mt][kb][1], aq[mt][kb][2], aq[mt][kb][3],
                        bk[kb][0], bk[kb][1]);

        const int key = kt * KT + n0 + 2 * tg;
        const unsigned char m0 = mask[b * Ll + key];
        const unsigned char m1 = mask[b * Ll + key + 1];
        #pragma unroll
        for (int mt = 0; mt < 2; mt++) {
            float s00 = m0 ? -1e9f : c[mt][0] * 0.125f;
            float s01 = m1 ? -1e9f : c[mt][1] * 0.125f;
            float s10 = m0 ? -1e9f : c[mt][2] * 0.125f;
            float s11 = m1 ? -1e9f : c[mt][3] * 0.125f;
            lm[mt * 2]     = fmaxf(lm[mt * 2],     fmaxf(s00, s01));
            lm[mt * 2 + 1] = fmaxf(lm[mt * 2 + 1], fmaxf(s10, s11));
            *(unsigned*)&Sh[(mt * 16 + g)     * SSTH + key] = f22h(s00, s01);
            *(unsigned*)&Sh[(mt * 16 + g + 8) * SSTH + key] = f22h(s10, s11);
        }
        __syncthreads();
    }

    #pragma unroll
    for (int i = 0; i < 4; i++) {
        lm[i] = fmaxf(lm[i], __shfl_xor_sync(0xffffffffu, lm[i], 1));
        lm[i] = fmaxf(lm[i], __shfl_xor_sync(0xffffffffu, lm[i], 2));
    }
    if (tg == 0) {
        atomicMax(&rowmaxU[g],      f2key(lm[0]));
        atomicMax(&rowmaxU[g + 8],  f2key(lm[1]));
        atomicMax(&rowmaxU[g + 16], f2key(lm[2]));
        atomicMax(&rowmaxU[g + 24], f2key(lm[3]));
    }
    __syncthreads();

    stage_tile(0, vbase, 0); CP_COMMIT();
    stage_tile(1, vbase, 1); CP_COMMIT();

    #pragma unroll
    for (int rr = 0; rr < 2; rr++) {
        const int r = 2 * w + rr;
        const float m = key2f(rowmaxU[r]);
        __half* Sr = Sh + r * SSTH;
        float sum = 0.f;
        #pragma unroll 4
        for (int i = 0; i < 32; i++) {
            const int cc = i * 64 + 2 * lane;
            __half2 hv = *(__half2*)&Sr[cc];
            float e0 = __expf(__half2float(hv.x) - m);
            float e1 = __expf(__half2float(hv.y) - m);
            sum += e0 + e1;
            *(unsigned*)&Sr[cc] = f22h(e0, e1);
        }
        #pragma unroll
        for (int o = 16; o; o >>= 1) sum += __shfl_xor_sync(0xffffffffu, sum, o);
        if (lane == 0) invl[r] = 1.f / sum;
    }
    __syncthreads();

    {
        float il[QT];
        #pragma unroll
        for (int r = 0; r < QT; r++) il[r] = invl[r];
        for (int k2 = 2 * t; k2 < Ll; k2 += 1024) {
            float a0 = 0.f, a1 = 0.f;
            #pragma unroll
            for (int r = 0; r < QT; r++) {
                __half2 p = *(__half2*)&Sh[r * SSTH + k2];
                a0 += __half2float(p.x) * il[r];
                a1 += __half2float(p.y) * il[r];
            }
            atomicAdd(&colsum[b * Ll + k2],     a0);
            atomicAdd(&colsum[b * Ll + k2 + 1], a1);
        }
    }

    const int sk = (w & 7) * 16;
    const int dh = (w >> 3) * 32;
    float c[2][4][4] = {};

    for (int vt = 0; vt < NKT; vt++) {
        CP_WAIT(1);
        __syncthreads();
        if (vt + 2 < NKT) stage_tile((vt + 2) % 3, vbase, vt + 2);
        CP_COMMIT();

        const unsigned kvb = shKV + (vt % 3) * (KVBUF * 2);

        unsigned ap[2][4];
        #pragma unroll
        for (int mt = 0; mt < 2; mt++)
            ldsm_x4(ap[mt][0], ap[mt][1], ap[mt][2], ap[mt][3],
                    shS + ((mt * 16 + arow) * SSTH + vt * KT + sk + acol) * 2);

        unsigned bv[2][4];
        #pragma unroll
        for (int nn = 0; nn < 2; nn++)
            ldsm_x4t(bv[nn][0], bv[nn][1], bv[nn][2], bv[nn][3],
                     kvb + ((sk + arow) * KVSTH + dh + nn * 16 + acol) * 2);

        #pragma unroll
        for (int mt = 0; mt < 2; mt++)
            #pragma unroll
            for (int ng = 0; ng < 4; ng++)
                mma_f16(c[mt][ng][0], c[mt][ng][1], c[mt][ng][2], c[mt][ng][3],
                        ap[mt][0], ap[mt][1], ap[mt][2], ap[mt][3],
                        bv[ng >> 1][(ng & 1) * 2], bv[ng >> 1][(ng & 1) * 2 + 1]);
    }
    __syncthreads();

    float* R = (float*)smb;
    const int slab = w & 7;
    #pragma unroll
    for (int mt = 0; mt < 2; mt++)
        #pragma unroll
        for (int ng = 0; ng < 4; ng++) {
            const int col = dh + ng * 8 + 2 * tg;
            *(float2*)&R[slab * RSLAB + (mt * 16 + g)     * RROW + col] = make_float2(c[mt][ng][0], c[mt][ng][1]);
            *(float2*)&R[slab * RSLAB + (mt * 16 + g + 8) * RROW + col] = make_float2(c[mt][ng][2], c[mt][ng][3]);
        }
    __syncthreads();

    for (int id = t; id < QT * DHd / 2; id += 512) {
        const int r  = id >> 5;
        const int d  = (id & 31) * 2;
        float s0 = 0.f, s1 = 0.f;
        #pragma unroll
        for (int sl = 0; sl < 8; sl++) {
            s0 += R[sl * RSLAB + r * RROW + d];
            s1 += R[sl * RSLAB + r * RROW + d + 1];
        }
        const float il = invl[r];
        *(unsigned*)&atted[(size_t)(b * Ll + q0 + r) * Hh + hd + d] = f22h(s0 * il, s1 * il);
    }
}

// ---------------- launch ----------------
extern "C" void kernel_launch(void* const* d_in, const int* in_sizes, int n_in,
                              void* d_out, int out_size)
{
    const float* v  = (const float*)d_in[0];
    const float* k  = (const float*)d_in[1];
    const float* q  = (const float*)d_in[2];
    const unsigned char* mask = (const unsigned char*)d_in[3];
    const float* Wv = (const float*)d_in[4];
    const float* bv = (const float*)d_in[5];
    const float* Wk = (const float*)d_in[6];
    const float* bk = (const float*)d_in[7];
    const float* Wq = (const float*)d_in[8];
    const float* bq = (const float*)d_in[9];
    const float* Wt = (const float*)d_in[10];
    const float* bt = (const float*)d_in[11];
    const float* Wm = (const float*)d_in[12];
    const float* bm = (const float*)d_in[13];
    float* out = (float*)d_out;

    __half *qh, *kh, *vh, *Wqh, *Wkh, *Wvh, *Wmh, *qp, *kp, *vp, *atted;
    float *thr, *colsum;
    cudaGetSymbolAddress((void**)&qh,  g_qh);
    cudaGetSymbolAddress((void**)&kh,  g_kh);
    cudaGetSymbolAddress((void**)&vh,  g_vh);
    cudaGetSymbolAddress((void**)&Wqh, g_Wqh);
    cudaGetSymbolAddress((void**)&Wkh, g_Wkh);
    cudaGetSymbolAddress((void**)&Wvh, g_Wvh);
    cudaGetSymbolAddress((void**)&Wmh, g_Wmh);
    cudaGetSymbolAddress((void**)&qp,  g_qp);
    cudaGetSymbolAddress((void**)&kp,  g_kp);
    cudaGetSymbolAddress((void**)&vp,  g_vp);
    cudaGetSymbolAddress((void**)&atted, g_atted);
    cudaGetSymbolAddress((void**)&thr,   g_thr);
    cudaGetSymbolAddress((void**)&colsum, g_colsum);

    cudaFuncSetAttribute(attn_kernel, cudaFuncAttributeMaxDynamicSharedMemorySize, ATTN_SMEM);
    cudaFuncSetAttribute(gemm_f16_kernel<__half, false>, cudaFuncAttributeMaxDynamicSharedMemorySize, GEMM_SMEM);
    cudaFuncSetAttribute(gemm_f16_kernel<float, true>,   cudaFuncAttributeMaxDynamicSharedMemorySize, GEMM_SMEM);

    cvt_all<<<8192, 256>>>(Wq, Wk, Wv, Wm, q, k, v, Wqh, Wkh, Wvh, Wmh, qh, kh, vh);

    gemm_f16_kernel<__half, false><<<dim3(8, 32, 3), 512, GEMM_SMEM>>>(
        qh, kh, vh, Wqh, Wkh, Wvh, bq, bk, bv, qp, kp, vp, nullptr, nullptr);

    threshold_kernel<<<GM, 128>>>(qp, kp, Wt, bt, thr, colsum);

    attn_kernel<<<Bb * NHh * (Ll / QT), 512, ATTN_SMEM>>>(qp, kp, vp, mask, atted, colsum);

    gemm_f16_kernel<float, true><<<dim3(8, 32, 1), 512, GEMM_SMEM>>>(
        atted, atted, atted, Wmh, Wmh, Wmh, bm, bm, bm, out, out, out, colsum, thr);
}